// round 14
// baseline (speedup 1.0000x reference)
#include <cuda_runtime.h>
#include <cuda.h>
#include <cuda_fp16.h>
#include <cstdint>

#define BB 4
#define NN 576
#define DM 512
#define DI 1024
#define DS 16
#define DTR 32
#define MT (BB*NN)   // 2304 tokens
#define NSPLIT 4

// ---------------- fp32 workspace (only split-K partials + x1) ----------------
#define SZ_X1   (MT*DM)
#define SZ_PART (2*NSPLIT*MT*64)
#define OFF_X1   0
#define OFF_PART (OFF_X1 + SZ_X1)
#define WS_TOTAL (OFF_PART + SZ_PART)

__device__ float g_ws[WS_TOTAL];

// ---------------- fp16 workspace ----------------
#define HOFF_XN   0
#define HOFF_XZ   (HOFF_XN + MT*DM)            // 2 dirs x MT x 2DI
#define HOFF_U    (HOFF_XZ + 2*MT*2*DI)        // 2 dirs x MT x DI
#define HOFF_DT   (HOFF_U + 2*MT*DI)           // 2 dirs x MT x DI
#define HOFF_XD   (HOFF_DT + 2*MT*DI)          // 2 dirs x MT x 64
#define HOFF_Y    (HOFF_XD + 2*MT*64)
#define HOFF_CAT  (HOFF_Y + 2*MT*DI)
#define HOFF_XN2  (HOFF_CAT + MT*2*DM)
#define HOFF_HFF  (HOFF_XN2 + MT*DM)
#define HOFF_WIN  (HOFF_HFF + MT*4*DM)
#define HOFF_WX   (HOFF_WIN + 2*2*DI*DM)
#define HOFF_WDT  (HOFF_WX + 2*64*DI)
#define HOFF_WO   (HOFF_WDT + 2*DI*64)
#define HOFF_MW   (HOFF_WO + 2*DM*DI)
#define HOFF_W1   (HOFF_MW + DM*2*DM)
#define HOFF_W2   (HOFF_W1 + 4*DM*DM)
#define H_TOTAL   (HOFF_W2 + DM*4*DM)

__device__ __align__(1024) __half g_wsh[H_TOTAL];

// ---------------- helpers ----------------
__device__ __forceinline__ float sigmoidf_(float x) { return 1.f / (1.f + __expf(-x)); }
__device__ __forceinline__ float softplusf_(float x) {
    return fmaxf(x, 0.f) + log1pf(__expf(-fabsf(x)));
}
__device__ __forceinline__ float gelu_tanh(float x) {
    float x3 = x * x * x;
    return 0.5f * x * (1.f + tanhf(0.7978845608028654f * (x + 0.044715f * x3)));
}

// ---------------- weight conversion (fp32 -> fp16, optional K padding) ----------------
struct Cvt { const float* s; __half* d; int rows; int sk; int dk; };
struct CvtTab { Cvt e[11]; };

__global__ void cvt_kernel(CvtTab tab) {
    Cvt c = tab.e[blockIdx.y];
    int total = c.rows * c.dk;
    for (int idx = blockIdx.x * 256 + threadIdx.x; idx < total; idx += gridDim.x * 256) {
        int row = idx / c.dk, col = idx - row * c.dk;
        float v = (col < c.sk) ? c.s[(size_t)row * c.sk + col] : 0.f;
        c.d[idx] = __float2half(v);
    }
}

// ---------------- LayerNorm (fp16 out) ----------------
__global__ void ln_kernel(const float* __restrict__ x, const float* __restrict__ g,
                          const float* __restrict__ b, __half* __restrict__ out) {
    int row = blockIdx.x;
    int t = threadIdx.x;              // 256 threads
    const float* xr = x + row * DM;
    float v0 = xr[t], v1 = xr[t + 256];
    float s = v0 + v1, q = v0 * v0 + v1 * v1;
    #pragma unroll
    for (int o = 16; o; o >>= 1) {
        s += __shfl_xor_sync(0xffffffffu, s, o);
        q += __shfl_xor_sync(0xffffffffu, q, o);
    }
    __shared__ float ss[8], qq[8];
    int w = t >> 5;
    if ((t & 31) == 0) { ss[w] = s; qq[w] = q; }
    __syncthreads();
    s = 0.f; q = 0.f;
    #pragma unroll
    for (int i = 0; i < 8; i++) { s += ss[i]; q += qq[i]; }
    float mean = s * (1.f / DM);
    float var = q * (1.f / DM) - mean * mean;
    float inv = rsqrtf(var + 1e-5f);
    out[row * DM + t]       = __float2half((v0 - mean) * inv * g[t] + b[t]);
    out[row * DM + t + 256] = __float2half((v1 - mean) * inv * g[t + 256] + b[t + 256]);
}

// ---------------- mbarrier / TMA primitives ----------------
#define MBINIT(addr, cnt) \
    asm volatile("mbarrier.init.shared.b64 [%0], %1;" :: "r"(addr), "r"(cnt) : "memory")
#define MBEXPECT(addr, bytes) \
    asm volatile("mbarrier.arrive.expect_tx.shared.b64 _, [%0], %1;" :: "r"(addr), "r"(bytes) : "memory")
#define MBARRIVE(addr) \
    asm volatile("mbarrier.arrive.shared.b64 _, [%0];" :: "r"(addr) : "memory")

__device__ __forceinline__ void mbar_wait(uint32_t addr, uint32_t phase) {
    asm volatile(
        "{\n\t.reg .pred p;\n\t"
        "LW%=:\n\t"
        "mbarrier.try_wait.parity.shared.b64 p, [%0], %1;\n\t"
        "@!p bra LW%=;\n\t}"
        :: "r"(addr), "r"(phase) : "memory");
}

__device__ __forceinline__ void tma2d(uint32_t dst, const CUtensorMap* m, int cx, int cy, uint32_t bar) {
    asm volatile(
        "cp.async.bulk.tensor.2d.shared::cta.global.tile.mbarrier::complete_tx::bytes "
        "[%0], [%1, {%2, %3}], [%4];"
        :: "r"(dst), "l"(m), "r"(cx), "r"(cy), "r"(bar) : "memory");
}

// ---------------- fp16 tensor-core GEMM (TMA + producer warp, 128xNTILE tile) ------------
// EPI: 0 none, 1 bias+softplus, 2 bias+residual, 3 bias+gelu ; OUTH: fp16 output
struct PtrSet {
    const float* bias;
    const float* resid;
    void* C;
};

__device__ __forceinline__ void mma16(float (&d)[4], const uint32_t (&a)[4], const uint32_t (&b)[2]) {
    asm volatile(
        "mma.sync.aligned.m16n8k16.row.col.f32.f16.f16.f32 "
        "{%0,%1,%2,%3}, {%4,%5,%6,%7}, {%8,%9}, {%0,%1,%2,%3};\n"
        : "+f"(d[0]), "+f"(d[1]), "+f"(d[2]), "+f"(d[3])
        : "r"(a[0]), "r"(a[1]), "r"(a[2]), "r"(a[3]),
          "r"(b[0]), "r"(b[1]));
}

__device__ __forceinline__ void ldsm4(uint32_t (&r)[4], uint32_t addr) {
    asm volatile("ldmatrix.sync.aligned.m8n8.x4.shared.b16 {%0,%1,%2,%3}, [%4];\n"
                 : "=r"(r[0]), "=r"(r[1]), "=r"(r[2]), "=r"(r[3]) : "r"(addr));
}

#define SLAB_A 16384u               // 128 rows x 128B (64 fp16/row)
#define NTHREADS 288                // 8 compute warps + 1 producer warp
#define SMEM_OF(NTILE, STGN) ((unsigned)(STGN) * (SLAB_A + (unsigned)(NTILE) * 128u) + 1024)

template <int EPI, int NTILE, int OUTH, int STGN, int OCC>
__global__ void __launch_bounds__(NTHREADS, OCC) mm_tma(
    const __grid_constant__ CUtensorMap mA0, const __grid_constant__ CUtensorMap mA1,
    const __grid_constant__ CUtensorMap mW0, const __grid_constant__ CUtensorMap mW1,
    PtrSet p0, PtrSet p1, int ldc, int coffStep, int N, int Ksplit,
    int kbaseStep, int csplitStep)
{
    extern __shared__ float dynsm[];
    __shared__ __align__(8) uint64_t mb[2 * STGN];   // full[0..S-1], empty[S..2S-1]

    constexpr uint32_t SLAB_B = (uint32_t)NTILE * 128u;
    constexpr uint32_t SST = SLAB_A + SLAB_B;
    constexpr int WN = NTILE / 2;
    constexpr int NTL = NTILE / 16;
    constexpr int NPQ = NTILE / 32;

    const int dir = blockIdx.z & 1;
    const int split = blockIdx.z >> 1;
    const CUtensorMap* tA = dir ? &mA1 : &mA0;
    const CUtensorMap* tW = dir ? &mW1 : &mW0;
    const PtrSet p = dir ? p1 : p0;
    const int coff = dir * coffStep;
    const int kbase = split * kbaseStep;

    const int tid = threadIdx.x;
    const int lane = tid & 31;
    const int wid = tid >> 5;        // 0..8
    const int wr = wid & 3;
    const int wc = (wid >> 2) & 1;
    const int g = lane >> 2;
    const int t = lane & 3;

    const int m0 = blockIdx.x * 128;
    const int n0 = blockIdx.y * NTILE;

    uint32_t raw = (uint32_t)__cvta_generic_to_shared(dynsm);
    const uint32_t sbase = (raw + 1023u) & ~1023u;
    const uint32_t mbb = (uint32_t)__cvta_generic_to_shared(&mb[0]);

    const int nc = Ksplit >> 6;   // chunks of K=64 fp16

    if (tid == 0) {
        #pragma unroll
        for (int s = 0; s < STGN; s++) {
            MBINIT(mbb + s * 8, 1);
            MBINIT(mbb + (STGN + s) * 8, 8);
        }
    }
    __syncthreads();

    if (wid == 8) {
        if (lane == 0) {
            for (int c = 0; c < nc; c++) {
                int s = c % STGN;
                uint32_t ph = 1u ^ (uint32_t)((c / STGN) & 1);
                mbar_wait(mbb + (STGN + s) * 8, ph);
                MBEXPECT(mbb + s * 8, SST);
                tma2d(sbase + s * SST,          tA, kbase + c * 64, m0, mbb + s * 8);
                tma2d(sbase + s * SST + SLAB_A, tW, kbase + c * 64, n0, mbb + s * 8);
            }
        }
    } else {
        const uint32_t asw = (uint32_t)((lane & 7) << 4);
        const uint32_t awb = (uint32_t)(wr * 4096 + (lane & 15) * 128);
        const uint32_t ua  = (uint32_t)(lane >> 4);
        const uint32_t bwb = (uint32_t)((wc * WN + (lane & 7) + ((lane >> 4) << 3)) * 128);
        const uint32_t ub  = (uint32_t)((lane >> 3) & 1);

        float d[2][NTL][4];
        #pragma unroll
        for (int i = 0; i < 2; i++)
            #pragma unroll
            for (int j = 0; j < NTL; j++)
                #pragma unroll
                for (int r = 0; r < 4; r++) d[i][j][r] = 0.f;

        for (int c = 0; c < nc; c++) {
            int s = c % STGN;
            mbar_wait(mbb + s * 8, (uint32_t)((c / STGN) & 1));
            const uint32_t sa = sbase + s * SST;
            const uint32_t sbB = sa + SLAB_A;
            #pragma unroll
            for (int kk = 0; kk < 4; kk++) {
                uint32_t a[2][4];
                uint32_t b[NTL][2];
                uint32_t aoff = (((ua + kk * 2) << 4) ^ asw);
                #pragma unroll
                for (int mt = 0; mt < 2; mt++)
                    ldsm4(a[mt], sa + awb + mt * 2048 + aoff);
                uint32_t boff = (((ub + kk * 2) << 4) ^ asw);
                #pragma unroll
                for (int np = 0; np < NPQ; np++) {
                    uint32_t r[4];
                    ldsm4(r, sbB + bwb + np * 2048 + boff);
                    b[2 * np][0] = r[0]; b[2 * np][1] = r[1];
                    b[2 * np + 1][0] = r[2]; b[2 * np + 1][1] = r[3];
                }
                if (kk == 3 && lane == 0) MBARRIVE(mbb + (STGN + s) * 8);
                #pragma unroll
                for (int mt = 0; mt < 2; mt++)
                    #pragma unroll
                    for (int nt = 0; nt < NTL; nt++)
                        mma16(d[mt][nt], a[mt], b[nt]);
            }
        }

        // -------- epilogue --------
        float* Cf = (float*)p.C + (size_t)split * csplitStep;
        __half* Ch = (__half*)p.C;
        #pragma unroll
        for (int mt = 0; mt < 2; mt++) {
            const int row = m0 + wr * 32 + mt * 16 + g;
            #pragma unroll
            for (int nt = 0; nt < NTL; nt++) {
                const int col = n0 + wc * WN + nt * 8 + 2 * t;
                if (col < N) {
                    float v00 = d[mt][nt][0], v01 = d[mt][nt][1];
                    float v10 = d[mt][nt][2], v11 = d[mt][nt][3];
                    if (EPI != 0) {
                        float bz0 = p.bias[col], bz1 = p.bias[col + 1];
                        v00 += bz0; v01 += bz1; v10 += bz0; v11 += bz1;
                    }
                    if (EPI == 1) {
                        v00 = softplusf_(v00); v01 = softplusf_(v01);
                        v10 = softplusf_(v10); v11 = softplusf_(v11);
                    } else if (EPI == 2) {
                        const float* r0 = p.resid + (size_t)row * ldc + coff + col;
                        const float* r1 = p.resid + (size_t)(row + 8) * ldc + coff + col;
                        v00 += r0[0]; v01 += r0[1]; v10 += r1[0]; v11 += r1[1];
                    } else if (EPI == 3) {
                        v00 = gelu_tanh(v00); v01 = gelu_tanh(v01);
                        v10 = gelu_tanh(v10); v11 = gelu_tanh(v11);
                    }
                    if (OUTH) {
                        *(__half2*)&Ch[(size_t)row * ldc + coff + col]       = __floats2half2_rn(v00, v01);
                        *(__half2*)&Ch[(size_t)(row + 8) * ldc + coff + col] = __floats2half2_rn(v10, v11);
                    } else {
                        *(float2*)&Cf[(size_t)row * ldc + coff + col]       = make_float2(v00, v01);
                        *(float2*)&Cf[(size_t)(row + 8) * ldc + coff + col] = make_float2(v10, v11);
                    }
                }
            }
        }
    }
}

// ---------------- split-K reduce for x-proj (fp16 out only) ----------------
__global__ void reduce_xd(const float* __restrict__ part, __half* __restrict__ xd16)
{
    int gid = blockIdx.x * 256 + threadIdx.x;
    if (gid >= 2 * MT * 64) return;
    int dir = gid / (MT * 64);
    int i = gid - dir * (MT * 64);
    const float* base = part + (size_t)dir * MT * 64 + i;
    float s = 0.f;
    #pragma unroll
    for (int sp = 0; sp < NSPLIT; sp++)
        s += base[(size_t)sp * 2 * MT * 64];
    xd16[gid] = __float2half(s);
}

// ---------------- depthwise causal conv + SiLU (fp16 in/out, 2 ch/thread) ----------------
__global__ void __launch_bounds__(256) conv_kernel(
    const __half* __restrict__ xz16a, const __half* __restrict__ xz16b,
    const float* __restrict__ w0, const float* __restrict__ w1,
    const float* __restrict__ cb0, const float* __restrict__ cb1,
    __half* __restrict__ u16)
{
    const int dir = blockIdx.y;
    const __half* xz = dir ? xz16b : xz16a;
    const float* w  = dir ? w1  : w0;
    const float* cb = dir ? cb1 : cb0;

    int i = blockIdx.x * 256 + threadIdx.x;   // over MT*DI/2
    if (i >= MT * (DI / 2)) return;
    int cp = i % (DI / 2);
    int row = i / (DI / 2);
    int n = row % NN, b = row / NN;
    int c = cp * 2;

    float4 w0v = *(const float4*)(w + c * 4);
    float4 w1v = *(const float4*)(w + (c + 1) * 4);
    float2 cbv = *(const float2*)(cb + c);
    float a0 = cbv.x, a1 = cbv.y;
    const __half* xbase = xz + (size_t)b * NN * 2 * DI + c;

    #pragma unroll
    for (int k = 0; k < 4; k++) {
        int nn = dir ? (n + 3 - k) : (n - 3 + k);
        if (nn >= 0 && nn < NN) {
            __half2 v = *(const __half2*)(xbase + (size_t)nn * 2 * DI);
            float2 vf = __half22float2(v);
            float wk0 = (k == 0) ? w0v.x : (k == 1) ? w0v.y : (k == 2) ? w0v.z : w0v.w;
            float wk1 = (k == 0) ? w1v.x : (k == 1) ? w1v.y : (k == 2) ? w1v.z : w1v.w;
            a0 += vf.x * wk0;
            a1 += vf.y * wk1;
        }
    }
    a0 *= sigmoidf_(a0);
    a1 *= sigmoidf_(a1);
    *(__half2*)(u16 + (size_t)dir * MT * DI + (size_t)row * DI + c) = __floats2half2_rn(a0, a1);
}

// ---------------- selective scan (paired steps, PF=8, fp16 in/out) ----------------
#define CPCOMMIT() asm volatile("cp.async.commit_group;\n")
#define CP8(dst, src) \
    asm volatile("cp.async.ca.shared.global [%0], [%1], 8;\n" :: "r"(dst), "l"(src))
#define PF 8
__global__ void __launch_bounds__(512, 1) scan_kernel(
    const __half* __restrict__ u16, const __half* __restrict__ dt16,
    const __half* __restrict__ xd16,
    const __half* __restrict__ xz16a, const __half* __restrict__ xz16b,
    const float* __restrict__ Al0, const float* __restrict__ Al1,
    const float* __restrict__ D0p, const float* __restrict__ D1p,
    __half* __restrict__ y16)
{
    const int dir = blockIdx.y;
    const __half* up   = u16 + (size_t)dir * MT * DI;
    const __half* dtp  = dt16 + (size_t)dir * MT * DI;
    const __half* xdp  = xd16 + (size_t)dir * MT * 64;
    const __half* xzp  = dir ? xz16b : xz16a;
    const float* Alog = dir ? Al1  : Al0;
    const float* Dp   = dir ? D1p  : D0p;
    __half* yp        = y16 + (size_t)dir * MT * DI;

    __shared__ __align__(16) __half sm[PF][224];
    const int bi = blockIdx.x >> 4;
    const int cb = (blockIdx.x & 15) << 6;
    const int tid = threadIdx.x;
    const int s = tid & 15;
    const int cl0 = tid >> 4;
    const int c0 = cb + cl0, c1 = c0 + 32;

    const float A0 = -__expf(Alog[c0 * DS + s]);
    const float A1 = -__expf(Alog[c1 * DS + s]);
    const float Dc0 = Dp[c0], Dc1 = Dp[c1];
    float h0 = 0.f, h1 = 0.f;

    auto issue = [&](int stage, int n) {
        if (tid < 56) {
            int row = bi * NN + n;
            const __half* src;
            int off;
            if (tid < 16)      { src = dtp + (size_t)row * DI + cb + tid * 4;                 off = tid * 4; }
            else if (tid < 32) { src = up  + (size_t)row * DI + cb + (tid - 16) * 4;          off = 64 + (tid - 16) * 4; }
            else if (tid < 48) { src = xzp + (size_t)row * 2 * DI + DI + cb + (tid - 32) * 4; off = 128 + (tid - 32) * 4; }
            else if (tid < 52) { src = xdp + (size_t)row * 64 + 32 + (tid - 48) * 4;          off = 192 + (tid - 48) * 4; }
            else               { src = xdp + (size_t)row * 64 + 48 + (tid - 52) * 4;          off = 208 + (tid - 52) * 4; }
            uint32_t d = (uint32_t)__cvta_generic_to_shared(&sm[stage][off]);
            CP8(d, src);
        }
    };
    #define NIDX(st) (dir ? (NN - 1 - (st)) : (st))

    issue(0, NIDX(0)); CPCOMMIT();
    issue(1, NIDX(1)); CPCOMMIT();
    issue(2, NIDX(2)); CPCOMMIT();
    issue(3, NIDX(3)); CPCOMMIT();

    for (int j = 0; j < NN; j += 2) {
        if (j + 4 < NN) issue((j + 4) & 7, NIDX(j + 4));
        CPCOMMIT();
        if (j + 5 < NN) issue((j + 5) & 7, NIDX(j + 5));
        CPCOMMIT();
        asm volatile("cp.async.wait_group 4;\n");
        __syncthreads();

        const __half* S0 = sm[j & 7];
        const __half* S1 = sm[(j + 1) & 7];

        float dta0 = __half2float(S0[cl0]),       dta1 = __half2float(S0[32 + cl0]);
        float dtb0 = __half2float(S1[cl0]),       dtb1 = __half2float(S1[32 + cl0]);
        float ua0  = __half2float(S0[64 + cl0]),  ua1  = __half2float(S0[96 + cl0]);
        float ub0  = __half2float(S1[64 + cl0]),  ub1  = __half2float(S1[96 + cl0]);
        float Ba = __half2float(S0[192 + s]), Ca = __half2float(S0[208 + s]);
        float Bb = __half2float(S1[192 + s]), Cb = __half2float(S1[208 + s]);

        float ea0 = __expf(dta0 * A0);
        float ea1 = __expf(dta1 * A1);
        float eb0 = __expf(dtb0 * A0);
        float eb1 = __expf(dtb1 * A1);

        h0 = ea0 * h0 + dta0 * Ba * ua0;
        h1 = ea1 * h1 + dta1 * Ba * ua1;
        float ya0 = h0 * Ca, ya1 = h1 * Ca;

        h0 = eb0 * h0 + dtb0 * Bb * ub0;
        h1 = eb1 * h1 + dtb1 * Bb * ub1;
        float yb0 = h0 * Cb, yb1 = h1 * Cb;

        #pragma unroll
        for (int o = 8; o; o >>= 1) {
            ya0 += __shfl_xor_sync(0xffffffffu, ya0, o);
            ya1 += __shfl_xor_sync(0xffffffffu, ya1, o);
            yb0 += __shfl_xor_sync(0xffffffffu, yb0, o);
            yb1 += __shfl_xor_sync(0xffffffffu, yb1, o);
        }
        if (s == 0) {
            int rowa = bi * NN + NIDX(j);
            int rowb = bi * NN + NIDX(j + 1);
            float za0 = __half2float(S0[128 + cl0]), za1 = __half2float(S0[160 + cl0]);
            float zb0 = __half2float(S1[128 + cl0]), zb1 = __half2float(S1[160 + cl0]);
            yp[(size_t)rowa * DI + c0] = __float2half((ya0 + ua0 * Dc0) * (za0 * sigmoidf_(za0)));
            yp[(size_t)rowa * DI + c1] = __float2half((ya1 + ua1 * Dc1) * (za1 * sigmoidf_(za1)));
            yp[(size_t)rowb * DI + c0] = __float2half((yb0 + ub0 * Dc0) * (zb0 * sigmoidf_(zb0)));
            yp[(size_t)rowb * DI + c1] = __float2half((yb1 + ub1 * Dc1) * (zb1 * sigmoidf_(zb1)));
        }
    }
    #undef NIDX
}

// ---------------- host: tensormap construction (fp16) ----------------
typedef CUresult (*PFN_encodeTiled)(
    CUtensorMap*, CUtensorMapDataType, cuuint32_t, void*,
    const cuuint64_t*, const cuuint64_t*, const cuuint32_t*, const cuuint32_t*,
    CUtensorMapInterleave, CUtensorMapSwizzle, CUtensorMapL2promotion,
    CUtensorMapFloatOOBfill);

static PFN_encodeTiled get_encoder() {
    static PFN_encodeTiled fn = nullptr;
    if (!fn) {
        void* p = nullptr;
        cudaDriverEntryPointQueryResult qr;
#if CUDART_VERSION >= 12050
        cudaGetDriverEntryPointByVersion("cuTensorMapEncodeTiled", &p, 12000,
                                         cudaEnableDefault, &qr);
#else
        cudaGetDriverEntryPoint("cuTensorMapEncodeTiled", &p, cudaEnableDefault, &qr);
#endif
        fn = (PFN_encodeTiled)p;
    }
    return fn;
}

static void enc_map16(CUtensorMap* m, const void* ptr, uint64_t d0, uint64_t d1, uint32_t b1) {
    cuuint64_t dims[2] = {d0, d1};
    cuuint64_t strides[1] = {d0 * 2};
    cuuint32_t box[2] = {64u, b1};
    cuuint32_t es[2] = {1u, 1u};
    get_encoder()(m, CU_TENSOR_MAP_DATA_TYPE_FLOAT16, 2, (void*)ptr,
                  dims, strides, box, es,
                  CU_TENSOR_MAP_INTERLEAVE_NONE, CU_TENSOR_MAP_SWIZZLE_128B,
                  CU_TENSOR_MAP_L2_PROMOTION_L2_128B, CU_TENSOR_MAP_FLOAT_OOB_FILL_NONE);
}

// ---------------- launch ----------------
extern "C" void kernel_launch(void* const* d_in, const int* in_sizes, int n_in,
                              void* d_out, int out_size) {
    const float* x  = (const float*)d_in[0];
    const float* g1 = (const float*)d_in[1];
    const float* b1 = (const float*)d_in[2];
    const float* g2 = (const float*)d_in[3];
    const float* b2 = (const float*)d_in[4];

    int base_f, base_r, base_m;
    if (in_sizes[5] == DM * 2 * DM) {        // merge_W first => dict order
        base_m = 5; base_f = 11; base_r = 20;
    } else {                                  // f_Win first => signature order
        base_f = 5; base_r = 14; base_m = 23;
    }
    const float *Win[2], *convw[2], *convb[2], *Wx[2], *Wdt[2], *bdt[2], *Alog[2], *Dp[2], *Wout[2];
    int bases[2] = {base_f, base_r};
    for (int d = 0; d < 2; d++) {
        int bs = bases[d];
        Win[d]   = (const float*)d_in[bs + 0];
        convw[d] = (const float*)d_in[bs + 1];
        convb[d] = (const float*)d_in[bs + 2];
        Wx[d]    = (const float*)d_in[bs + 3];
        Wdt[d]   = (const float*)d_in[bs + 4];
        bdt[d]   = (const float*)d_in[bs + 5];
        Alog[d]  = (const float*)d_in[bs + 6];
        Dp[d]    = (const float*)d_in[bs + 7];
        Wout[d]  = (const float*)d_in[bs + 8];
    }
    const float* merge_W = (const float*)d_in[base_m + 0];
    const float* merge_b = (const float*)d_in[base_m + 1];
    const float* ffn_W1  = (const float*)d_in[base_m + 2];
    const float* ffn_b1  = (const float*)d_in[base_m + 3];
    const float* ffn_W2  = (const float*)d_in[base_m + 4];
    const float* ffn_b2  = (const float*)d_in[base_m + 5];

    float* ws = nullptr;
    cudaGetSymbolAddress((void**)&ws, g_ws);
    __half* wh = nullptr;
    cudaGetSymbolAddress((void**)&wh, g_wsh);

    float* x1  = ws + OFF_X1;
    float* part = ws + OFF_PART;

    __half* xn16   = wh + HOFF_XN;
    __half* xz16   = wh + HOFF_XZ;
    __half* u16    = wh + HOFF_U;
    __half* dt16   = wh + HOFF_DT;
    __half* xd16   = wh + HOFF_XD;
    __half* y16    = wh + HOFF_Y;
    __half* cat16  = wh + HOFF_CAT;
    __half* xn216  = wh + HOFF_XN2;
    __half* hff16  = wh + HOFF_HFF;
    __half* Win16  = wh + HOFF_WIN;
    __half* Wx16   = wh + HOFF_WX;
    __half* Wdt16  = wh + HOFF_WDT;
    __half* Wo16   = wh + HOFF_WO;
    __half* mW16   = wh + HOFF_MW;
    __half* W116   = wh + HOFF_W1;
    __half* W216   = wh + HOFF_W2;

    cudaFuncSetAttribute((void*)mm_tma<0,128,1,3,2>, cudaFuncAttributeMaxDynamicSharedMemorySize, SMEM_OF(128,3));
    cudaFuncSetAttribute((void*)mm_tma<1,128,1,3,2>, cudaFuncAttributeMaxDynamicSharedMemorySize, SMEM_OF(128,3));
    cudaFuncSetAttribute((void*)mm_tma<3,128,1,3,2>, cudaFuncAttributeMaxDynamicSharedMemorySize, SMEM_OF(128,3));
    cudaFuncSetAttribute((void*)mm_tma<0,64,0,3,3>,  cudaFuncAttributeMaxDynamicSharedMemorySize, SMEM_OF(64,3));
    cudaFuncSetAttribute((void*)mm_tma<0,64,1,3,3>,  cudaFuncAttributeMaxDynamicSharedMemorySize, SMEM_OF(64,3));
    cudaFuncSetAttribute((void*)mm_tma<2,64,0,3,3>,  cudaFuncAttributeMaxDynamicSharedMemorySize, SMEM_OF(64,3));

    // ---- weight conversion (fp32 -> fp16) ----
    {
        CvtTab tab;
        tab.e[0]  = {Win[0],  Win16,                2 * DI, DM,   DM};
        tab.e[1]  = {Win[1],  Win16 + 2 * DI * DM,  2 * DI, DM,   DM};
        tab.e[2]  = {Wx[0],   Wx16,                 64,     DI,   DI};
        tab.e[3]  = {Wx[1],   Wx16 + 64 * DI,       64,     DI,   DI};
        tab.e[4]  = {Wdt[0],  Wdt16,                DI,     DTR,  64};
        tab.e[5]  = {Wdt[1],  Wdt16 + DI * 64,      DI,     DTR,  64};
        tab.e[6]  = {Wout[0], Wo16,                 DM,     DI,   DI};
        tab.e[7]  = {Wout[1], Wo16 + DM * DI,       DM,     DI,   DI};
        tab.e[8]  = {merge_W, mW16,                 DM,     2*DM, 2*DM};
        tab.e[9]  = {ffn_W1,  W116,                 4 * DM, DM,   DM};
        tab.e[10] = {ffn_W2,  W216,                 DM,     4*DM, 4*DM};
        cvt_kernel<<<dim3(256, 11), 256>>>(tab);
    }

    // ---- tensormaps (all fp16) ----
    CUtensorMap map_xn, map_Win0, map_Win1, map_u0, map_u1, map_Wx0, map_Wx1;
    CUtensorMap map_xd0, map_xd1, map_Wdt0, map_Wdt1, map_y0, map_y1, map_Wo0, map_Wo1;
    CUtensorMap map_cat, map_mW, map_xn2, map_W1, map_hff, map_W2;
    enc_map16(&map_xn,  xn16,             DM,     MT,   128);
    enc_map16(&map_Win0, Win16,           DM,     2*DI, 128);
    enc_map16(&map_Win1, Win16 + 2*DI*DM, DM,     2*DI, 128);
    enc_map16(&map_u0,  u16,              DI,     MT,   128);
    enc_map16(&map_u1,  u16 + MT*DI,      DI,     MT,   128);
    enc_map16(&map_Wx0, Wx16,             DI,     64,   64);
    enc_map16(&map_Wx1, Wx16 + 64*DI,     DI,     64,   64);
    enc_map16(&map_xd0, xd16,             64,     MT,   128);
    enc_map16(&map_xd1, xd16 + MT*64,     64,     MT,   128);
    enc_map16(&map_Wdt0, Wdt16,           64,     DI,   128);
    enc_map16(&map_Wdt1, Wdt16 + DI*64,   64,     DI,   128);
    enc_map16(&map_y0,  y16,              DI,     MT,   128);
    enc_map16(&map_y1,  y16 + MT*DI,      DI,     MT,   128);
    enc_map16(&map_Wo0, Wo16,             DI,     DM,   64);
    enc_map16(&map_Wo1, Wo16 + DM*DI,     DI,     DM,   64);
    enc_map16(&map_cat, cat16,            2*DM,   MT,   128);
    enc_map16(&map_mW,  mW16,             2*DM,   DM,   64);
    enc_map16(&map_xn2, xn216,            DM,     MT,   128);
    enc_map16(&map_W1,  W116,             DM,     4*DM, 128);
    enc_map16(&map_hff, hff16,            4*DM,   MT,   128);
    enc_map16(&map_W2,  W216,             4*DM,   DM,   64);

    const int MTB = MT / 128;  // 18

    ln_kernel<<<MT, 256>>>(x, g1, b1, xn16);

    // in-proj both dirs: N=2048, K=512 -> xz16
    {
        PtrSet a{nullptr, nullptr, xz16};
        PtrSet b{nullptr, nullptr, xz16 + (size_t)MT * 2 * DI};
        mm_tma<0,128,1,3,2><<<dim3(MTB, 16, 2), NTHREADS, SMEM_OF(128,3)>>>(
            map_xn, map_xn, map_Win0, map_Win1, a, b, 2 * DI, 0, 2 * DI, DM, 0, 0);
    }

    conv_kernel<<<dim3((MT * DI / 2 + 255) / 256, 2), 256>>>(
        xz16, xz16 + (size_t)MT * 2 * DI, convw[0], convw[1], convb[0], convb[1], u16);

    // x-proj: N=64, split-K=4 -> part fp32
    {
        PtrSet a{nullptr, nullptr, part};
        PtrSet b{nullptr, nullptr, part + (size_t)MT * 64};
        mm_tma<0,64,0,3,3><<<dim3(MTB, 1, 2 * NSPLIT), NTHREADS, SMEM_OF(64,3)>>>(
            map_u0, map_u1, map_Wx0, map_Wx1, a, b, 64, 0, 64, DI / NSPLIT,
            DI / NSPLIT, 2 * MT * 64);
    }
    reduce_xd<<<(2 * MT * 64 + 255) / 256, 256>>>(part, xd16);

    // dt-proj + softplus: N=1024, K=64 (padded) -> dt16
    {
        PtrSet a{bdt[0], nullptr, dt16};
        PtrSet b{bdt[1], nullptr, dt16 + (size_t)MT * DI};
        mm_tma<1,128,1,3,2><<<dim3(MTB, 8, 2), NTHREADS, SMEM_OF(128,3)>>>(
            map_xd0, map_xd1, map_Wdt0, map_Wdt1, a, b, DI, 0, DI, 64, 0, 0);
    }

    scan_kernel<<<dim3(BB * (DI / 64), 2), 512>>>(
        u16, dt16, xd16, xz16, xz16 + (size_t)MT * 2 * DI,
        Alog[0], Alog[1], Dp[0], Dp[1], y16);

    // out-proj both dirs -> cat16, N=512 per dir
    {
        PtrSet a{nullptr, nullptr, cat16};
        PtrSet b{nullptr, nullptr, cat16};
        mm_tma<0,64,1,3,3><<<dim3(MTB, 8, 2), NTHREADS, SMEM_OF(64,3)>>>(
            map_y0, map_y1, map_Wo0, map_Wo1, a, b, 2 * DM, DM, DM, DI, 0, 0);
    }

    // merge + residual -> x1 fp32
    {
        PtrSet a{merge_b, x, x1};
        mm_tma<2,64,0,3,3><<<dim3(MTB, 8, 1), NTHREADS, SMEM_OF(64,3)>>>(
            map_cat, map_cat, map_mW, map_mW, a, a, DM, 0, DM, 2 * DM, 0, 0);
    }

    ln_kernel<<<MT, 256>>>(x1, g2, b2, xn216);

    // ffn1 + gelu -> hff16
    {
        PtrSet a{ffn_b1, nullptr, hff16};
        mm_tma<3,128,1,3,2><<<dim3(MTB, 16, 1), NTHREADS, SMEM_OF(128,3)>>>(
            map_xn2, map_xn2, map_W1, map_W1, a, a, 4 * DM, 0, 4 * DM, DM, 0, 0);
    }
    // ffn2 + residual -> out fp32
    {
        PtrSet a{ffn_b2, x1, (float*)d_out};
        mm_tma<2,64,0,3,3><<<dim3(MTB, 8, 1), NTHREADS, SMEM_OF(64,3)>>>(
            map_hff, map_hff, map_W2, map_W2, a, a, DM, 0, DM, 4 * DM, 0, 0);
    }
}

// round 15
// speedup vs baseline: 1.0139x; 1.0139x over previous
#include <cuda_runtime.h>
#include <cuda.h>
#include <cuda_fp16.h>
#include <cstdint>

#define BB 4
#define NN 576
#define DM 512
#define DI 1024
#define DS 16
#define DTR 32
#define MT (BB*NN)   // 2304 tokens
#define NSPLIT 4

// ---------------- fp32 workspace ----------------
#define SZ_X1   (MT*DM)
#define SZ_PART (2*NSPLIT*MT*64)
#define OFF_X1   0
#define OFF_PART (OFF_X1 + SZ_X1)
#define WS_TOTAL (OFF_PART + SZ_PART)

__device__ float g_ws[WS_TOTAL];

// ---------------- fp16 workspace ----------------
#define HOFF_XN   0
#define HOFF_XZ   (HOFF_XN + MT*DM)
#define HOFF_U    (HOFF_XZ + 2*MT*2*DI)
#define HOFF_DT   (HOFF_U + 2*MT*DI)
#define HOFF_XD   (HOFF_DT + 2*MT*DI)
#define HOFF_Y    (HOFF_XD + 2*MT*64)
#define HOFF_F    (HOFF_Y + 2*MT*DI)           // F0,F1: 2 x DM x DI
#define HOFF_XN2  (HOFF_F + 2*DM*DI)
#define HOFF_HFF  (HOFF_XN2 + MT*DM)
#define HOFF_WIN  (HOFF_HFF + MT*4*DM)
#define HOFF_WX   (HOFF_WIN + 2*2*DI*DM)
#define HOFF_WDT  (HOFF_WX + 2*64*DI)
#define HOFF_WOT  (HOFF_WDT + 2*DI*64)         // Wout transposed: 2 x DI x DM
#define HOFF_MW   (HOFF_WOT + 2*DI*DM)
#define HOFF_W1   (HOFF_MW + DM*2*DM)
#define HOFF_W2   (HOFF_W1 + 4*DM*DM)
#define H_TOTAL   (HOFF_W2 + DM*4*DM)

__device__ __align__(1024) __half g_wsh[H_TOTAL];

// ---------------- helpers ----------------
__device__ __forceinline__ float sigmoidf_(float x) { return 1.f / (1.f + __expf(-x)); }
__device__ __forceinline__ float softplusf_(float x) {
    return fmaxf(x, 0.f) + log1pf(__expf(-fabsf(x)));
}
__device__ __forceinline__ float gelu_tanh(float x) {
    float x3 = x * x * x;
    return 0.5f * x * (1.f + tanhf(0.7978845608028654f * (x + 0.044715f * x3)));
}

// ---------------- weight conversion (fp32 -> fp16, optional K padding) ----------------
struct Cvt { const float* s; __half* d; int rows; int sk; int dk; };
struct CvtTab { Cvt e[9]; };

__global__ void cvt_kernel(CvtTab tab) {
    Cvt c = tab.e[blockIdx.y];
    int total = c.rows * c.dk;
    for (int idx = blockIdx.x * 256 + threadIdx.x; idx < total; idx += gridDim.x * 256) {
        int row = idx / c.dk, col = idx - row * c.dk;
        float v = (col < c.sk) ? c.s[(size_t)row * c.sk + col] : 0.f;
        c.d[idx] = __float2half(v);
    }
}

// ---------------- tiled transpose+convert of Wout: (DM x DI) fp32 -> (DI x DM) fp16 -----
__global__ void transpose_wo(const float* __restrict__ w0, const float* __restrict__ w1,
                             __half* __restrict__ o)
{
    __shared__ float tile[32][33];
    int dir = blockIdx.z;
    const float* w = dir ? w1 : w0;
    int e0 = blockIdx.x * 32;   // e: Wout row (0..DM)
    int k0 = blockIdx.y * 32;   // k: Wout col (0..DI)
    int tx = threadIdx.x, ty = threadIdx.y;    // 32 x 8
    #pragma unroll
    for (int j = 0; j < 32; j += 8)
        tile[ty + j][tx] = w[(size_t)(e0 + ty + j) * DI + k0 + tx];
    __syncthreads();
    __half* dst = o + (size_t)dir * DI * DM;
    #pragma unroll
    for (int j = 0; j < 32; j += 8)
        dst[(size_t)(k0 + ty + j) * DM + e0 + tx] = __float2half(tile[tx][ty + j]);
}

// ---------------- LayerNorm (fp16 out) ----------------
__global__ void ln_kernel(const float* __restrict__ x, const float* __restrict__ g,
                          const float* __restrict__ b, __half* __restrict__ out) {
    int row = blockIdx.x;
    int t = threadIdx.x;              // 256 threads
    const float* xr = x + row * DM;
    float v0 = xr[t], v1 = xr[t + 256];
    float s = v0 + v1, q = v0 * v0 + v1 * v1;
    #pragma unroll
    for (int o = 16; o; o >>= 1) {
        s += __shfl_xor_sync(0xffffffffu, s, o);
        q += __shfl_xor_sync(0xffffffffu, q, o);
    }
    __shared__ float ss[8], qq[8];
    int w = t >> 5;
    if ((t & 31) == 0) { ss[w] = s; qq[w] = q; }
    __syncthreads();
    s = 0.f; q = 0.f;
    #pragma unroll
    for (int i = 0; i < 8; i++) { s += ss[i]; q += qq[i]; }
    float mean = s * (1.f / DM);
    float var = q * (1.f / DM) - mean * mean;
    float inv = rsqrtf(var + 1e-5f);
    out[row * DM + t]       = __float2half((v0 - mean) * inv * g[t] + b[t]);
    out[row * DM + t + 256] = __float2half((v1 - mean) * inv * g[t + 256] + b[t + 256]);
}

// ---------------- mbarrier / TMA primitives ----------------
#define MBINIT(addr, cnt) \
    asm volatile("mbarrier.init.shared.b64 [%0], %1;" :: "r"(addr), "r"(cnt) : "memory")
#define MBEXPECT(addr, bytes) \
    asm volatile("mbarrier.arrive.expect_tx.shared.b64 _, [%0], %1;" :: "r"(addr), "r"(bytes) : "memory")
#define MBARRIVE(addr) \
    asm volatile("mbarrier.arrive.shared.b64 _, [%0];" :: "r"(addr) : "memory")

__device__ __forceinline__ void mbar_wait(uint32_t addr, uint32_t phase) {
    asm volatile(
        "{\n\t.reg .pred p;\n\t"
        "LW%=:\n\t"
        "mbarrier.try_wait.parity.shared.b64 p, [%0], %1;\n\t"
        "@!p bra LW%=;\n\t}"
        :: "r"(addr), "r"(phase) : "memory");
}

__device__ __forceinline__ void tma2d(uint32_t dst, const CUtensorMap* m, int cx, int cy, uint32_t bar) {
    asm volatile(
        "cp.async.bulk.tensor.2d.shared::cta.global.tile.mbarrier::complete_tx::bytes "
        "[%0], [%1, {%2, %3}], [%4];"
        :: "r"(dst), "l"(m), "r"(cx), "r"(cy), "r"(bar) : "memory");
}

// ---------------- fp16 tensor-core GEMM (TMA + producer warp, 128xNTILE tile) ------------
// EPI: 0 none, 1 bias+softplus, 2 bias+residual, 3 bias+gelu ; OUTH: fp16 output
// DUALK: K loop covers (mA0,mW0) then (mA1,mW1), accumulating (fused dual GEMM)
struct PtrSet {
    const float* bias;
    const float* resid;
    void* C;
};

__device__ __forceinline__ void mma16(float (&d)[4], const uint32_t (&a)[4], const uint32_t (&b)[2]) {
    asm volatile(
        "mma.sync.aligned.m16n8k16.row.col.f32.f16.f16.f32 "
        "{%0,%1,%2,%3}, {%4,%5,%6,%7}, {%8,%9}, {%0,%1,%2,%3};\n"
        : "+f"(d[0]), "+f"(d[1]), "+f"(d[2]), "+f"(d[3])
        : "r"(a[0]), "r"(a[1]), "r"(a[2]), "r"(a[3]),
          "r"(b[0]), "r"(b[1]));
}

__device__ __forceinline__ void ldsm4(uint32_t (&r)[4], uint32_t addr) {
    asm volatile("ldmatrix.sync.aligned.m8n8.x4.shared.b16 {%0,%1,%2,%3}, [%4];\n"
                 : "=r"(r[0]), "=r"(r[1]), "=r"(r[2]), "=r"(r[3]) : "r"(addr));
}

#define SLAB_A 16384u               // 128 rows x 128B (64 fp16/row)
#define NTHREADS 288                // 8 compute warps + 1 producer warp
#define SMEM_OF(NTILE, STGN) ((unsigned)(STGN) * (SLAB_A + (unsigned)(NTILE) * 128u) + 1024)

template <int EPI, int NTILE, int OUTH, int STGN, int DUALK>
__global__ void __launch_bounds__(NTHREADS, 2) mm_tma(
    const __grid_constant__ CUtensorMap mA0, const __grid_constant__ CUtensorMap mA1,
    const __grid_constant__ CUtensorMap mW0, const __grid_constant__ CUtensorMap mW1,
    PtrSet p0, PtrSet p1, int ldc, int coffStep, int N, int Ksplit,
    int kbaseStep, int csplitStep)
{
    extern __shared__ float dynsm[];
    __shared__ __align__(8) uint64_t mb[2 * STGN];

    constexpr uint32_t SLAB_B = (uint32_t)NTILE * 128u;
    constexpr uint32_t SST = SLAB_A + SLAB_B;
    constexpr int WN = NTILE / 2;
    constexpr int NTL = NTILE / 16;
    constexpr int NPQ = NTILE / 32;

    const int dir = blockIdx.z & 1;
    const int split = blockIdx.z >> 1;
    const CUtensorMap* tA = dir ? &mA1 : &mA0;
    const CUtensorMap* tW = dir ? &mW1 : &mW0;
    const PtrSet p = dir ? p1 : p0;
    const int coff = dir * coffStep;
    const int kbase = split * kbaseStep;

    const int tid = threadIdx.x;
    const int lane = tid & 31;
    const int wid = tid >> 5;
    const int wr = wid & 3;
    const int wc = (wid >> 2) & 1;
    const int g = lane >> 2;
    const int t = lane & 3;

    const int m0 = blockIdx.x * 128;
    const int n0 = blockIdx.y * NTILE;

    uint32_t raw = (uint32_t)__cvta_generic_to_shared(dynsm);
    const uint32_t sbase = (raw + 1023u) & ~1023u;
    const uint32_t mbb = (uint32_t)__cvta_generic_to_shared(&mb[0]);

    const int ncH = Ksplit >> 6;
    const int nc = DUALK ? (2 * ncH) : ncH;

    if (tid == 0) {
        #pragma unroll
        for (int s = 0; s < STGN; s++) {
            MBINIT(mbb + s * 8, 1);
            MBINIT(mbb + (STGN + s) * 8, 8);
        }
    }
    __syncthreads();

    if (wid == 8) {
        if (lane == 0) {
            for (int c = 0; c < nc; c++) {
                int s = c % STGN;
                uint32_t ph = 1u ^ (uint32_t)((c / STGN) & 1);
                mbar_wait(mbb + (STGN + s) * 8, ph);
                MBEXPECT(mbb + s * 8, SST);
                const CUtensorMap* cA = tA;
                const CUtensorMap* cW = tW;
                int cx = kbase + c * 64;
                if (DUALK) {
                    if (c >= ncH) { cA = &mA1; cW = &mW1; cx = (c - ncH) * 64; }
                    else          { cA = &mA0; cW = &mW0; cx = c * 64; }
                }
                tma2d(sbase + s * SST,          cA, cx, m0, mbb + s * 8);
                tma2d(sbase + s * SST + SLAB_A, cW, cx, n0, mbb + s * 8);
            }
        }
    } else {
        const uint32_t asw = (uint32_t)((lane & 7) << 4);
        const uint32_t awb = (uint32_t)(wr * 4096 + (lane & 15) * 128);
        const uint32_t ua  = (uint32_t)(lane >> 4);
        const uint32_t bwb = (uint32_t)((wc * WN + (lane & 7) + ((lane >> 4) << 3)) * 128);
        const uint32_t ub  = (uint32_t)((lane >> 3) & 1);

        float d[2][NTL][4];
        #pragma unroll
        for (int i = 0; i < 2; i++)
            #pragma unroll
            for (int j = 0; j < NTL; j++)
                #pragma unroll
                for (int r = 0; r < 4; r++) d[i][j][r] = 0.f;

        for (int c = 0; c < nc; c++) {
            int s = c % STGN;
            mbar_wait(mbb + s * 8, (uint32_t)((c / STGN) & 1));
            const uint32_t sa = sbase + s * SST;
            const uint32_t sbB = sa + SLAB_A;
            #pragma unroll
            for (int kk = 0; kk < 4; kk++) {
                uint32_t a[2][4];
                uint32_t b[NTL][2];
                uint32_t aoff = (((ua + kk * 2) << 4) ^ asw);
                #pragma unroll
                for (int mt = 0; mt < 2; mt++)
                    ldsm4(a[mt], sa + awb + mt * 2048 + aoff);
                uint32_t boff = (((ub + kk * 2) << 4) ^ asw);
                #pragma unroll
                for (int np = 0; np < NPQ; np++) {
                    uint32_t r[4];
                    ldsm4(r, sbB + bwb + np * 2048 + boff);
                    b[2 * np][0] = r[0]; b[2 * np][1] = r[1];
                    b[2 * np + 1][0] = r[2]; b[2 * np + 1][1] = r[3];
                }
                if (kk == 3 && lane == 0) MBARRIVE(mbb + (STGN + s) * 8);
                #pragma unroll
                for (int mt = 0; mt < 2; mt++)
                    #pragma unroll
                    for (int nt = 0; nt < NTL; nt++)
                        mma16(d[mt][nt], a[mt], b[nt]);
            }
        }

        // -------- epilogue --------
        float* Cf = (float*)p.C + (size_t)split * csplitStep;
        __half* Ch = (__half*)p.C;
        #pragma unroll
        for (int mt = 0; mt < 2; mt++) {
            const int row = m0 + wr * 32 + mt * 16 + g;
            #pragma unroll
            for (int nt = 0; nt < NTL; nt++) {
                const int col = n0 + wc * WN + nt * 8 + 2 * t;
                if (col < N) {
                    float v00 = d[mt][nt][0], v01 = d[mt][nt][1];
                    float v10 = d[mt][nt][2], v11 = d[mt][nt][3];
                    if (EPI != 0) {
                        float bz0 = p.bias[col], bz1 = p.bias[col + 1];
                        v00 += bz0; v01 += bz1; v10 += bz0; v11 += bz1;
                    }
                    if (EPI == 1) {
                        v00 = softplusf_(v00); v01 = softplusf_(v01);
                        v10 = softplusf_(v10); v11 = softplusf_(v11);
                    } else if (EPI == 2) {
                        const float* r0 = p.resid + (size_t)row * ldc + coff + col;
                        const float* r1 = p.resid + (size_t)(row + 8) * ldc + coff + col;
                        v00 += r0[0]; v01 += r0[1]; v10 += r1[0]; v11 += r1[1];
                    } else if (EPI == 3) {
                        v00 = gelu_tanh(v00); v01 = gelu_tanh(v01);
                        v10 = gelu_tanh(v10); v11 = gelu_tanh(v11);
                    }
                    if (OUTH) {
                        *(__half2*)&Ch[(size_t)row * ldc + coff + col]       = __floats2half2_rn(v00, v01);
                        *(__half2*)&Ch[(size_t)(row + 8) * ldc + coff + col] = __floats2half2_rn(v10, v11);
                    } else {
                        *(float2*)&Cf[(size_t)row * ldc + coff + col]       = make_float2(v00, v01);
                        *(float2*)&Cf[(size_t)(row + 8) * ldc + coff + col] = make_float2(v10, v11);
                    }
                }
            }
        }
    }
}

// ---------------- split-K reduce for x-proj (fp16 out only) ----------------
__global__ void reduce_xd(const float* __restrict__ part, __half* __restrict__ xd16)
{
    int gid = blockIdx.x * 256 + threadIdx.x;
    if (gid >= 2 * MT * 64) return;
    int dir = gid / (MT * 64);
    int i = gid - dir * (MT * 64);
    const float* base = part + (size_t)dir * MT * 64 + i;
    float s = 0.f;
    #pragma unroll
    for (int sp = 0; sp < NSPLIT; sp++)
        s += base[(size_t)sp * 2 * MT * 64];
    xd16[gid] = __float2half(s);
}

// ---------------- depthwise causal conv + SiLU (fp16 in/out, 2 ch/thread) ----------------
__global__ void __launch_bounds__(256) conv_kernel(
    const __half* __restrict__ xz16a, const __half* __restrict__ xz16b,
    const float* __restrict__ w0, const float* __restrict__ w1,
    const float* __restrict__ cb0, const float* __restrict__ cb1,
    __half* __restrict__ u16)
{
    const int dir = blockIdx.y;
    const __half* xz = dir ? xz16b : xz16a;
    const float* w  = dir ? w1  : w0;
    const float* cb = dir ? cb1 : cb0;

    int i = blockIdx.x * 256 + threadIdx.x;   // over MT*DI/2
    if (i >= MT * (DI / 2)) return;
    int cp = i % (DI / 2);
    int row = i / (DI / 2);
    int n = row % NN, b = row / NN;
    int c = cp * 2;

    float4 w0v = *(const float4*)(w + c * 4);
    float4 w1v = *(const float4*)(w + (c + 1) * 4);
    float2 cbv = *(const float2*)(cb + c);
    float a0 = cbv.x, a1 = cbv.y;
    const __half* xbase = xz + (size_t)b * NN * 2 * DI + c;

    #pragma unroll
    for (int k = 0; k < 4; k++) {
        int nn = dir ? (n + 3 - k) : (n - 3 + k);
        if (nn >= 0 && nn < NN) {
            __half2 v = *(const __half2*)(xbase + (size_t)nn * 2 * DI);
            float2 vf = __half22float2(v);
            float wk0 = (k == 0) ? w0v.x : (k == 1) ? w0v.y : (k == 2) ? w0v.z : w0v.w;
            float wk1 = (k == 0) ? w1v.x : (k == 1) ? w1v.y : (k == 2) ? w1v.z : w1v.w;
            a0 += vf.x * wk0;
            a1 += vf.y * wk1;
        }
    }
    a0 *= sigmoidf_(a0);
    a1 *= sigmoidf_(a1);
    *(__half2*)(u16 + (size_t)dir * MT * DI + (size_t)row * DI + c) = __floats2half2_rn(a0, a1);
}

// ---------------- selective scan (paired steps, PF=8, fp16 in/out) ----------------
#define CPCOMMIT() asm volatile("cp.async.commit_group;\n")
#define CP8(dst, src) \
    asm volatile("cp.async.ca.shared.global [%0], [%1], 8;\n" :: "r"(dst), "l"(src))
#define PF 8
__global__ void __launch_bounds__(512, 1) scan_kernel(
    const __half* __restrict__ u16, const __half* __restrict__ dt16,
    const __half* __restrict__ xd16,
    const __half* __restrict__ xz16a, const __half* __restrict__ xz16b,
    const float* __restrict__ Al0, const float* __restrict__ Al1,
    const float* __restrict__ D0p, const float* __restrict__ D1p,
    __half* __restrict__ y16)
{
    const int dir = blockIdx.y;
    const __half* up   = u16 + (size_t)dir * MT * DI;
    const __half* dtp  = dt16 + (size_t)dir * MT * DI;
    const __half* xdp  = xd16 + (size_t)dir * MT * 64;
    const __half* xzp  = dir ? xz16b : xz16a;
    const float* Alog = dir ? Al1  : Al0;
    const float* Dp   = dir ? D1p  : D0p;
    __half* yp        = y16 + (size_t)dir * MT * DI;

    __shared__ __align__(16) __half sm[PF][224];
    const int bi = blockIdx.x >> 4;
    const int cb = (blockIdx.x & 15) << 6;
    const int tid = threadIdx.x;
    const int s = tid & 15;
    const int cl0 = tid >> 4;
    const int c0 = cb + cl0, c1 = c0 + 32;

    const float A0 = -__expf(Alog[c0 * DS + s]);
    const float A1 = -__expf(Alog[c1 * DS + s]);
    const float Dc0 = Dp[c0], Dc1 = Dp[c1];
    float h0 = 0.f, h1 = 0.f;

    auto issue = [&](int stage, int n) {
        if (tid < 56) {
            int row = bi * NN + n;
            const __half* src;
            int off;
            if (tid < 16)      { src = dtp + (size_t)row * DI + cb + tid * 4;                 off = tid * 4; }
            else if (tid < 32) { src = up  + (size_t)row * DI + cb + (tid - 16) * 4;          off = 64 + (tid - 16) * 4; }
            else if (tid < 48) { src = xzp + (size_t)row * 2 * DI + DI + cb + (tid - 32) * 4; off = 128 + (tid - 32) * 4; }
            else if (tid < 52) { src = xdp + (size_t)row * 64 + 32 + (tid - 48) * 4;          off = 192 + (tid - 48) * 4; }
            else               { src = xdp + (size_t)row * 64 + 48 + (tid - 52) * 4;          off = 208 + (tid - 52) * 4; }
            uint32_t d = (uint32_t)__cvta_generic_to_shared(&sm[stage][off]);
            CP8(d, src);
        }
    };
    #define NIDX(st) (dir ? (NN - 1 - (st)) : (st))

    issue(0, NIDX(0)); CPCOMMIT();
    issue(1, NIDX(1)); CPCOMMIT();
    issue(2, NIDX(2)); CPCOMMIT();
    issue(3, NIDX(3)); CPCOMMIT();

    for (int j = 0; j < NN; j += 2) {
        if (j + 4 < NN) issue((j + 4) & 7, NIDX(j + 4));
        CPCOMMIT();
        if (j + 5 < NN) issue((j + 5) & 7, NIDX(j + 5));
        CPCOMMIT();
        asm volatile("cp.async.wait_group 4;\n");
        __syncthreads();

        const __half* S0 = sm[j & 7];
        const __half* S1 = sm[(j + 1) & 7];

        float dta0 = __half2float(S0[cl0]),       dta1 = __half2float(S0[32 + cl0]);
        float dtb0 = __half2float(S1[cl0]),       dtb1 = __half2float(S1[32 + cl0]);
        float ua0  = __half2float(S0[64 + cl0]),  ua1  = __half2float(S0[96 + cl0]);
        float ub0  = __half2float(S1[64 + cl0]),  ub1  = __half2float(S1[96 + cl0]);
        float Ba = __half2float(S0[192 + s]), Ca = __half2float(S0[208 + s]);
        float Bb = __half2float(S1[192 + s]), Cb = __half2float(S1[208 + s]);

        float ea0 = __expf(dta0 * A0);
        float ea1 = __expf(dta1 * A1);
        float eb0 = __expf(dtb0 * A0);
        float eb1 = __expf(dtb1 * A1);

        h0 = ea0 * h0 + dta0 * Ba * ua0;
        h1 = ea1 * h1 + dta1 * Ba * ua1;
        float ya0 = h0 * Ca, ya1 = h1 * Ca;

        h0 = eb0 * h0 + dtb0 * Bb * ub0;
        h1 = eb1 * h1 + dtb1 * Bb * ub1;
        float yb0 = h0 * Cb, yb1 = h1 * Cb;

        #pragma unroll
        for (int o = 8; o; o >>= 1) {
            ya0 += __shfl_xor_sync(0xffffffffu, ya0, o);
            ya1 += __shfl_xor_sync(0xffffffffu, ya1, o);
            yb0 += __shfl_xor_sync(0xffffffffu, yb0, o);
            yb1 += __shfl_xor_sync(0xffffffffu, yb1, o);
        }
        if (s == 0) {
            int rowa = bi * NN + NIDX(j);
            int rowb = bi * NN + NIDX(j + 1);
            float za0 = __half2float(S0[128 + cl0]), za1 = __half2float(S0[160 + cl0]);
            float zb0 = __half2float(S1[128 + cl0]), zb1 = __half2float(S1[160 + cl0]);
            yp[(size_t)rowa * DI + c0] = __float2half((ya0 + ua0 * Dc0) * (za0 * sigmoidf_(za0)));
            yp[(size_t)rowa * DI + c1] = __float2half((ya1 + ua1 * Dc1) * (za1 * sigmoidf_(za1)));
            yp[(size_t)rowb * DI + c0] = __float2half((yb0 + ub0 * Dc0) * (zb0 * sigmoidf_(zb0)));
            yp[(size_t)rowb * DI + c1] = __float2half((yb1 + ub1 * Dc1) * (zb1 * sigmoidf_(zb1)));
        }
    }
    #undef NIDX
}

// ---------------- host: tensormap construction (fp16) ----------------
typedef CUresult (*PFN_encodeTiled)(
    CUtensorMap*, CUtensorMapDataType, cuuint32_t, void*,
    const cuuint64_t*, const cuuint64_t*, const cuuint32_t*, const cuuint32_t*,
    CUtensorMapInterleave, CUtensorMapSwizzle, CUtensorMapL2promotion,
    CUtensorMapFloatOOBfill);

static PFN_encodeTiled get_encoder() {
    static PFN_encodeTiled fn = nullptr;
    if (!fn) {
        void* p = nullptr;
        cudaDriverEntryPointQueryResult qr;
#if CUDART_VERSION >= 12050
        cudaGetDriverEntryPointByVersion("cuTensorMapEncodeTiled", &p, 12000,
                                         cudaEnableDefault, &qr);
#else
        cudaGetDriverEntryPoint("cuTensorMapEncodeTiled", &p, cudaEnableDefault, &qr);
#endif
        fn = (PFN_encodeTiled)p;
    }
    return fn;
}

static void enc_map16s(CUtensorMap* m, const void* ptr, uint64_t d0, uint64_t d1,
                       uint64_t ld, uint32_t b1) {
    cuuint64_t dims[2] = {d0, d1};
    cuuint64_t strides[1] = {ld * 2};
    cuuint32_t box[2] = {64u, b1};
    cuuint32_t es[2] = {1u, 1u};
    get_encoder()(m, CU_TENSOR_MAP_DATA_TYPE_FLOAT16, 2, (void*)ptr,
                  dims, strides, box, es,
                  CU_TENSOR_MAP_INTERLEAVE_NONE, CU_TENSOR_MAP_SWIZZLE_128B,
                  CU_TENSOR_MAP_L2_PROMOTION_L2_128B, CU_TENSOR_MAP_FLOAT_OOB_FILL_NONE);
}
static void enc_map16(CUtensorMap* m, const void* ptr, uint64_t d0, uint64_t d1, uint32_t b1) {
    enc_map16s(m, ptr, d0, d1, d0, b1);
}

// ---------------- launch ----------------
extern "C" void kernel_launch(void* const* d_in, const int* in_sizes, int n_in,
                              void* d_out, int out_size) {
    const float* x  = (const float*)d_in[0];
    const float* g1 = (const float*)d_in[1];
    const float* b1 = (const float*)d_in[2];
    const float* g2 = (const float*)d_in[3];
    const float* b2 = (const float*)d_in[4];

    int base_f, base_r, base_m;
    if (in_sizes[5] == DM * 2 * DM) {        // merge_W first => dict order
        base_m = 5; base_f = 11; base_r = 20;
    } else {                                  // f_Win first => signature order
        base_f = 5; base_r = 14; base_m = 23;
    }
    const float *Win[2], *convw[2], *convb[2], *Wx[2], *Wdt[2], *bdt[2], *Alog[2], *Dp[2], *Wout[2];
    int bases[2] = {base_f, base_r};
    for (int d = 0; d < 2; d++) {
        int bs = bases[d];
        Win[d]   = (const float*)d_in[bs + 0];
        convw[d] = (const float*)d_in[bs + 1];
        convb[d] = (const float*)d_in[bs + 2];
        Wx[d]    = (const float*)d_in[bs + 3];
        Wdt[d]   = (const float*)d_in[bs + 4];
        bdt[d]   = (const float*)d_in[bs + 5];
        Alog[d]  = (const float*)d_in[bs + 6];
        Dp[d]    = (const float*)d_in[bs + 7];
        Wout[d]  = (const float*)d_in[bs + 8];
    }
    const float* merge_W = (const float*)d_in[base_m + 0];
    const float* merge_b = (const float*)d_in[base_m + 1];
    const float* ffn_W1  = (const float*)d_in[base_m + 2];
    const float* ffn_b1  = (const float*)d_in[base_m + 3];
    const float* ffn_W2  = (const float*)d_in[base_m + 4];
    const float* ffn_b2  = (const float*)d_in[base_m + 5];

    float* ws = nullptr;
    cudaGetSymbolAddress((void**)&ws, g_ws);
    __half* wh = nullptr;
    cudaGetSymbolAddress((void**)&wh, g_wsh);

    float* x1  = ws + OFF_X1;
    float* part = ws + OFF_PART;

    __half* xn16   = wh + HOFF_XN;
    __half* xz16   = wh + HOFF_XZ;
    __half* u16    = wh + HOFF_U;
    __half* dt16   = wh + HOFF_DT;
    __half* xd16   = wh + HOFF_XD;
    __half* y16    = wh + HOFF_Y;
    __half* F016   = wh + HOFF_F;
    __half* F116   = F016 + (size_t)DM * DI;
    __half* xn216  = wh + HOFF_XN2;
    __half* hff16  = wh + HOFF_HFF;
    __half* Win16  = wh + HOFF_WIN;
    __half* Wx16   = wh + HOFF_WX;
    __half* Wdt16  = wh + HOFF_WDT;
    __half* WoT16  = wh + HOFF_WOT;
    __half* mW16   = wh + HOFF_MW;
    __half* W116   = wh + HOFF_W1;
    __half* W216   = wh + HOFF_W2;

    cudaFuncSetAttribute((void*)mm_tma<0,128,1,3,0>, cudaFuncAttributeMaxDynamicSharedMemorySize, SMEM_OF(128,3));
    cudaFuncSetAttribute((void*)mm_tma<1,128,1,3,0>, cudaFuncAttributeMaxDynamicSharedMemorySize, SMEM_OF(128,3));
    cudaFuncSetAttribute((void*)mm_tma<3,128,1,3,0>, cudaFuncAttributeMaxDynamicSharedMemorySize, SMEM_OF(128,3));
    cudaFuncSetAttribute((void*)mm_tma<0,64,0,4,0>,  cudaFuncAttributeMaxDynamicSharedMemorySize, SMEM_OF(64,4));
    cudaFuncSetAttribute((void*)mm_tma<2,64,0,4,1>,  cudaFuncAttributeMaxDynamicSharedMemorySize, SMEM_OF(64,4));
    cudaFuncSetAttribute((void*)mm_tma<2,64,0,4,0>,  cudaFuncAttributeMaxDynamicSharedMemorySize, SMEM_OF(64,4));

    // ---- weight conversion (fp32 -> fp16) ----
    {
        CvtTab tab;
        tab.e[0] = {Win[0],  Win16,                2 * DI, DM,   DM};
        tab.e[1] = {Win[1],  Win16 + 2 * DI * DM,  2 * DI, DM,   DM};
        tab.e[2] = {Wx[0],   Wx16,                 64,     DI,   DI};
        tab.e[3] = {Wx[1],   Wx16 + 64 * DI,       64,     DI,   DI};
        tab.e[4] = {Wdt[0],  Wdt16,                DI,     DTR,  64};
        tab.e[5] = {Wdt[1],  Wdt16 + DI * 64,      DI,     DTR,  64};
        tab.e[6] = {merge_W, mW16,                 DM,     2*DM, 2*DM};
        tab.e[7] = {ffn_W1,  W116,                 4 * DM, DM,   DM};
        tab.e[8] = {ffn_W2,  W216,                 DM,     4*DM, 4*DM};
        cvt_kernel<<<dim3(256, 9), 256>>>(tab);
    }
    transpose_wo<<<dim3(DM / 32, DI / 32, 2), dim3(32, 8)>>>(Wout[0], Wout[1], WoT16);

    // ---- tensormaps (all fp16) ----
    CUtensorMap map_xn, map_Win0, map_Win1, map_u0, map_u1, map_Wx0, map_Wx1;
    CUtensorMap map_xd0, map_xd1, map_Wdt0, map_Wdt1, map_y0, map_y1;
    CUtensorMap map_mWl, map_mWr, map_WoT0, map_WoT1, map_F0, map_F1;
    CUtensorMap map_xn2, map_W1, map_hff, map_W2;
    enc_map16(&map_xn,  xn16,             DM,     MT,   128);
    enc_map16(&map_Win0, Win16,           DM,     2*DI, 128);
    enc_map16(&map_Win1, Win16 + 2*DI*DM, DM,     2*DI, 128);
    enc_map16(&map_u0,  u16,              DI,     MT,   128);
    enc_map16(&map_u1,  u16 + MT*DI,      DI,     MT,   128);
    enc_map16(&map_Wx0, Wx16,             DI,     64,   64);
    enc_map16(&map_Wx1, Wx16 + 64*DI,     DI,     64,   64);
    enc_map16(&map_xd0, xd16,             64,     MT,   128);
    enc_map16(&map_xd1, xd16 + MT*64,     64,     MT,   128);
    enc_map16(&map_Wdt0, Wdt16,           64,     DI,   128);
    enc_map16(&map_Wdt1, Wdt16 + DI*64,   64,     DI,   128);
    enc_map16(&map_y0,  y16,              DI,     MT,   128);
    enc_map16(&map_y1,  y16 + MT*DI,      DI,     MT,   128);
    // F-prep: A = mW halves (rows d=512, K=e=512, row stride 2DM); W = WoT (rows k=1024, K=e=512)
    enc_map16s(&map_mWl, mW16,       DM, DM, 2*DM, 128);
    enc_map16s(&map_mWr, mW16 + DM,  DM, DM, 2*DM, 128);
    enc_map16(&map_WoT0, WoT16,           DM, DI, 128);
    enc_map16(&map_WoT1, WoT16 + DI*DM,   DM, DI, 128);
    // fused out+merge: W = F (rows d=512, K=k=1024)
    enc_map16(&map_F0,  F016,             DI, DM, 64);
    enc_map16(&map_F1,  F116,             DI, DM, 64);
    enc_map16(&map_xn2, xn216,            DM,     MT,   128);
    enc_map16(&map_W1,  W116,             DM,     4*DM, 128);
    enc_map16(&map_hff, hff16,            4*DM,   MT,   128);
    enc_map16(&map_W2,  W216,             4*DM,   DM,   64);

    const int MTB = MT / 128;  // 18

    // F-prep: F[d,k] = sum_e mW_half[d,e] * WoT[k,e];  M=512, N=1024, K=512
    {
        PtrSet a{nullptr, nullptr, F016};
        PtrSet b{nullptr, nullptr, F116};
        mm_tma<0,128,1,3,0><<<dim3(4, 8, 2), NTHREADS, SMEM_OF(128,3)>>>(
            map_mWl, map_mWr, map_WoT0, map_WoT1, a, b, DI, 0, DI, DM, 0, 0);
    }

    ln_kernel<<<MT, 256>>>(x, g1, b1, xn16);

    // in-proj both dirs: N=2048, K=512 -> xz16
    {
        PtrSet a{nullptr, nullptr, xz16};
        PtrSet b{nullptr, nullptr, xz16 + (size_t)MT * 2 * DI};
        mm_tma<0,128,1,3,0><<<dim3(MTB, 16, 2), NTHREADS, SMEM_OF(128,3)>>>(
            map_xn, map_xn, map_Win0, map_Win1, a, b, 2 * DI, 0, 2 * DI, DM, 0, 0);
    }

    conv_kernel<<<dim3((MT * DI / 2 + 255) / 256, 2), 256>>>(
        xz16, xz16 + (size_t)MT * 2 * DI, convw[0], convw[1], convb[0], convb[1], u16);

    // x-proj: N=64, split-K=4 -> part fp32
    {
        PtrSet a{nullptr, nullptr, part};
        PtrSet b{nullptr, nullptr, part + (size_t)MT * 64};
        mm_tma<0,64,0,4,0><<<dim3(MTB, 1, 2 * NSPLIT), NTHREADS, SMEM_OF(64,4)>>>(
            map_u0, map_u1, map_Wx0, map_Wx1, a, b, 64, 0, 64, DI / NSPLIT,
            DI / NSPLIT, 2 * MT * 64);
    }
    reduce_xd<<<(2 * MT * 64 + 255) / 256, 256>>>(part, xd16);

    // dt-proj + softplus: N=1024, K=64 (padded) -> dt16
    {
        PtrSet a{bdt[0], nullptr, dt16};
        PtrSet b{bdt[1], nullptr, dt16 + (size_t)MT * DI};
        mm_tma<1,128,1,3,0><<<dim3(MTB, 8, 2), NTHREADS, SMEM_OF(128,3)>>>(
            map_xd0, map_xd1, map_Wdt0, map_Wdt1, a, b, DI, 0, DI, 64, 0, 0);
    }

    scan_kernel<<<dim3(BB * (DI / 64), 2), 512>>>(
        u16, dt16, xd16, xz16, xz16 + (size_t)MT * 2 * DI,
        Alog[0], Alog[1], Dp[0], Dp[1], y16);

    // fused out-proj + merge + residual: x1 = y0*F0^T + y1*F1^T + mb + x  (DUALK)
    {
        PtrSet a{merge_b, x, x1};
        mm_tma<2,64,0,4,1><<<dim3(MTB, 8, 1), NTHREADS, SMEM_OF(64,4)>>>(
            map_y0, map_y1, map_F0, map_F1, a, a, DM, 0, DM, DI, 0, 0);
    }

    ln_kernel<<<MT, 256>>>(x1, g2, b2, xn216);

    // ffn1 + gelu -> hff16
    {
        PtrSet a{ffn_b1, nullptr, hff16};
        mm_tma<3,128,1,3,0><<<dim3(MTB, 16, 1), NTHREADS, SMEM_OF(128,3)>>>(
            map_xn2, map_xn2, map_W1, map_W1, a, a, 4 * DM, 0, 4 * DM, DM, 0, 0);
    }
    // ffn2 + residual -> out fp32
    {
        PtrSet a{ffn_b2, x1, (float*)d_out};
        mm_tma<2,64,0,4,0><<<dim3(MTB, 8, 1), NTHREADS, SMEM_OF(64,4)>>>(
            map_hff, map_hff, map_W2, map_W2, a, a, DM, 0, DM, 4 * DM, 0, 0);
    }
}

// round 16
// speedup vs baseline: 1.0722x; 1.0575x over previous
#include <cuda_runtime.h>
#include <cuda.h>
#include <cuda_fp16.h>
#include <cstdint>

#define BB 4
#define NN 576
#define DM 512
#define DI 1024
#define DS 16
#define DTR 32
#define MT (BB*NN)   // 2304 tokens
#define NSPLIT 4

// ---------------- fp32 workspace ----------------
#define SZ_X1   (MT*DM)
#define SZ_PART (2*NSPLIT*MT*64)
#define OFF_X1   0
#define OFF_PART (OFF_X1 + SZ_X1)
#define WS_TOTAL (OFF_PART + SZ_PART)

__device__ float g_ws[WS_TOTAL];

// ---------------- fp16 workspace ----------------
#define HOFF_XN   0
#define HOFF_XZ   (HOFF_XN + MT*DM)
#define HOFF_U    (HOFF_XZ + 2*MT*2*DI)
#define HOFF_DT   (HOFF_U + 2*MT*DI)
#define HOFF_XD   (HOFF_DT + 2*MT*DI)
#define HOFF_Y    (HOFF_XD + 2*MT*64)
#define HOFF_CAT  (HOFF_Y + 2*MT*DI)
#define HOFF_XN2  (HOFF_CAT + MT*2*DM)
#define HOFF_HFF  (HOFF_XN2 + MT*DM)
#define HOFF_WIN  (HOFF_HFF + MT*4*DM)
#define HOFF_WX   (HOFF_WIN + 2*2*DI*DM)
#define HOFF_WDT  (HOFF_WX + 2*64*DI)
#define HOFF_WO   (HOFF_WDT + 2*DI*64)
#define HOFF_MW   (HOFF_WO + 2*DM*DI)
#define HOFF_W1   (HOFF_MW + DM*2*DM)
#define HOFF_W2   (HOFF_W1 + 4*DM*DM)
#define H_TOTAL   (HOFF_W2 + DM*4*DM)

__device__ __align__(1024) __half g_wsh[H_TOTAL];

// ---------------- helpers ----------------
__device__ __forceinline__ float sigmoidf_(float x) { return 1.f / (1.f + __expf(-x)); }
__device__ __forceinline__ float softplusf_(float x) {
    return fmaxf(x, 0.f) + log1pf(__expf(-fabsf(x)));
}
__device__ __forceinline__ float gelu_tanh(float x) {
    float x3 = x * x * x;
    return 0.5f * x * (1.f + tanhf(0.7978845608028654f * (x + 0.044715f * x3)));
}

// ---------------- weight conversion (fp32 -> fp16, optional K padding) ----------------
struct Cvt { const float* s; __half* d; int rows; int sk; int dk; };
struct CvtTab { Cvt e[11]; };

__global__ void cvt_kernel(CvtTab tab) {
    Cvt c = tab.e[blockIdx.y];
    int total = c.rows * c.dk;
    for (int idx = blockIdx.x * 256 + threadIdx.x; idx < total; idx += gridDim.x * 256) {
        int row = idx / c.dk, col = idx - row * c.dk;
        float v = (col < c.sk) ? c.s[(size_t)row * c.sk + col] : 0.f;
        c.d[idx] = __float2half(v);
    }
}

// ---------------- LayerNorm (fp16 out) ----------------
__global__ void ln_kernel(const float* __restrict__ x, const float* __restrict__ g,
                          const float* __restrict__ b, __half* __restrict__ out) {
    int row = blockIdx.x;
    int t = threadIdx.x;              // 256 threads
    const float* xr = x + row * DM;
    float v0 = xr[t], v1 = xr[t + 256];
    float s = v0 + v1, q = v0 * v0 + v1 * v1;
    #pragma unroll
    for (int o = 16; o; o >>= 1) {
        s += __shfl_xor_sync(0xffffffffu, s, o);
        q += __shfl_xor_sync(0xffffffffu, q, o);
    }
    __shared__ float ss[8], qq[8];
    int w = t >> 5;
    if ((t & 31) == 0) { ss[w] = s; qq[w] = q; }
    __syncthreads();
    s = 0.f; q = 0.f;
    #pragma unroll
    for (int i = 0; i < 8; i++) { s += ss[i]; q += qq[i]; }
    float mean = s * (1.f / DM);
    float var = q * (1.f / DM) - mean * mean;
    float inv = rsqrtf(var + 1e-5f);
    out[row * DM + t]       = __float2half((v0 - mean) * inv * g[t] + b[t]);
    out[row * DM + t + 256] = __float2half((v1 - mean) * inv * g[t + 256] + b[t + 256]);
}

// ---------------- mbarrier / TMA primitives ----------------
#define MBINIT(addr, cnt) \
    asm volatile("mbarrier.init.shared.b64 [%0], %1;" :: "r"(addr), "r"(cnt) : "memory")
#define MBEXPECT(addr, bytes) \
    asm volatile("mbarrier.arrive.expect_tx.shared.b64 _, [%0], %1;" :: "r"(addr), "r"(bytes) : "memory")
#define MBARRIVE(addr) \
    asm volatile("mbarrier.arrive.shared.b64 _, [%0];" :: "r"(addr) : "memory")

__device__ __forceinline__ void mbar_wait(uint32_t addr, uint32_t phase) {
    asm volatile(
        "{\n\t.reg .pred p;\n\t"
        "LW%=:\n\t"
        "mbarrier.try_wait.parity.shared.b64 p, [%0], %1;\n\t"
        "@!p bra LW%=;\n\t}"
        :: "r"(addr), "r"(phase) : "memory");
}

__device__ __forceinline__ void tma2d(uint32_t dst, const CUtensorMap* m, int cx, int cy, uint32_t bar) {
    asm volatile(
        "cp.async.bulk.tensor.2d.shared::cta.global.tile.mbarrier::complete_tx::bytes "
        "[%0], [%1, {%2, %3}], [%4];"
        :: "r"(dst), "l"(m), "r"(cx), "r"(cy), "r"(bar) : "memory");
}

// ---------------- fp16 tensor-core GEMM (TMA + producer warp, 128xNTILE tile) ------------
// EPI: 0 none, 1 bias+softplus, 2 bias+residual, 3 bias+gelu ; OUTH: fp16 output
struct PtrSet {
    const float* bias;
    const float* resid;
    void* C;
};

__device__ __forceinline__ void mma16(float (&d)[4], const uint32_t (&a)[4], const uint32_t (&b)[2]) {
    asm volatile(
        "mma.sync.aligned.m16n8k16.row.col.f32.f16.f16.f32 "
        "{%0,%1,%2,%3}, {%4,%5,%6,%7}, {%8,%9}, {%0,%1,%2,%3};\n"
        : "+f"(d[0]), "+f"(d[1]), "+f"(d[2]), "+f"(d[3])
        : "r"(a[0]), "r"(a[1]), "r"(a[2]), "r"(a[3]),
          "r"(b[0]), "r"(b[1]));
}

__device__ __forceinline__ void ldsm4(uint32_t (&r)[4], uint32_t addr) {
    asm volatile("ldmatrix.sync.aligned.m8n8.x4.shared.b16 {%0,%1,%2,%3}, [%4];\n"
                 : "=r"(r[0]), "=r"(r[1]), "=r"(r[2]), "=r"(r[3]) : "r"(addr));
}

#define SLAB_A 16384u               // 128 rows x 128B (64 fp16/row)
#define NTHREADS 288                // 8 compute warps + 1 producer warp
#define SMEM_OF(NTILE, STGN) ((unsigned)(STGN) * (SLAB_A + (unsigned)(NTILE) * 128u) + 1024)

template <int EPI, int NTILE, int OUTH, int STGN>
__global__ void __launch_bounds__(NTHREADS, 2) mm_tma(
    const __grid_constant__ CUtensorMap mA0, const __grid_constant__ CUtensorMap mA1,
    const __grid_constant__ CUtensorMap mW0, const __grid_constant__ CUtensorMap mW1,
    PtrSet p0, PtrSet p1, int ldc, int coffStep, int N, int Ksplit,
    int kbaseStep, int csplitStep)
{
    extern __shared__ float dynsm[];
    __shared__ __align__(8) uint64_t mb[2 * STGN];

    constexpr uint32_t SLAB_B = (uint32_t)NTILE * 128u;
    constexpr uint32_t SST = SLAB_A + SLAB_B;
    constexpr int WN = NTILE / 2;
    constexpr int NTL = NTILE / 16;
    constexpr int NPQ = NTILE / 32;

    const int dir = blockIdx.z & 1;
    const int split = blockIdx.z >> 1;
    const CUtensorMap* tA = dir ? &mA1 : &mA0;
    const CUtensorMap* tW = dir ? &mW1 : &mW0;
    const PtrSet p = dir ? p1 : p0;
    const int coff = dir * coffStep;
    const int kbase = split * kbaseStep;

    const int tid = threadIdx.x;
    const int lane = tid & 31;
    const int wid = tid >> 5;
    const int wr = wid & 3;
    const int wc = (wid >> 2) & 1;
    const int g = lane >> 2;
    const int t = lane & 3;

    const int m0 = blockIdx.x * 128;
    const int n0 = blockIdx.y * NTILE;

    uint32_t raw = (uint32_t)__cvta_generic_to_shared(dynsm);
    const uint32_t sbase = (raw + 1023u) & ~1023u;
    const uint32_t mbb = (uint32_t)__cvta_generic_to_shared(&mb[0]);

    const int nc = Ksplit >> 6;

    if (tid == 0) {
        #pragma unroll
        for (int s = 0; s < STGN; s++) {
            MBINIT(mbb + s * 8, 1);
            MBINIT(mbb + (STGN + s) * 8, 8);
        }
    }
    __syncthreads();

    if (wid == 8) {
        if (lane == 0) {
            for (int c = 0; c < nc; c++) {
                int s = c % STGN;
                uint32_t ph = 1u ^ (uint32_t)((c / STGN) & 1);
                mbar_wait(mbb + (STGN + s) * 8, ph);
                MBEXPECT(mbb + s * 8, SST);
                tma2d(sbase + s * SST,          tA, kbase + c * 64, m0, mbb + s * 8);
                tma2d(sbase + s * SST + SLAB_A, tW, kbase + c * 64, n0, mbb + s * 8);
            }
        }
    } else {
        const uint32_t asw = (uint32_t)((lane & 7) << 4);
        const uint32_t awb = (uint32_t)(wr * 4096 + (lane & 15) * 128);
        const uint32_t ua  = (uint32_t)(lane >> 4);
        const uint32_t bwb = (uint32_t)((wc * WN + (lane & 7) + ((lane >> 4) << 3)) * 128);
        const uint32_t ub  = (uint32_t)((lane >> 3) & 1);

        float d[2][NTL][4];
        #pragma unroll
        for (int i = 0; i < 2; i++)
            #pragma unroll
            for (int j = 0; j < NTL; j++)
                #pragma unroll
                for (int r = 0; r < 4; r++) d[i][j][r] = 0.f;

        for (int c = 0; c < nc; c++) {
            int s = c % STGN;
            mbar_wait(mbb + s * 8, (uint32_t)((c / STGN) & 1));
            const uint32_t sa = sbase + s * SST;
            const uint32_t sbB = sa + SLAB_A;
            #pragma unroll
            for (int kk = 0; kk < 4; kk++) {
                uint32_t a[2][4];
                uint32_t b[NTL][2];
                uint32_t aoff = (((ua + kk * 2) << 4) ^ asw);
                #pragma unroll
                for (int mt = 0; mt < 2; mt++)
                    ldsm4(a[mt], sa + awb + mt * 2048 + aoff);
                uint32_t boff = (((ub + kk * 2) << 4) ^ asw);
                #pragma unroll
                for (int np = 0; np < NPQ; np++) {
                    uint32_t r[4];
                    ldsm4(r, sbB + bwb + np * 2048 + boff);
                    b[2 * np][0] = r[0]; b[2 * np][1] = r[1];
                    b[2 * np + 1][0] = r[2]; b[2 * np + 1][1] = r[3];
                }
                if (kk == 3 && lane == 0) MBARRIVE(mbb + (STGN + s) * 8);
                #pragma unroll
                for (int mt = 0; mt < 2; mt++)
                    #pragma unroll
                    for (int nt = 0; nt < NTL; nt++)
                        mma16(d[mt][nt], a[mt], b[nt]);
            }
        }

        // -------- epilogue --------
        float* Cf = (float*)p.C + (size_t)split * csplitStep;
        __half* Ch = (__half*)p.C;
        #pragma unroll
        for (int mt = 0; mt < 2; mt++) {
            const int row = m0 + wr * 32 + mt * 16 + g;
            #pragma unroll
            for (int nt = 0; nt < NTL; nt++) {
                const int col = n0 + wc * WN + nt * 8 + 2 * t;
                if (col < N) {
                    float v00 = d[mt][nt][0], v01 = d[mt][nt][1];
                    float v10 = d[mt][nt][2], v11 = d[mt][nt][3];
                    if (EPI != 0) {
                        float bz0 = p.bias[col], bz1 = p.bias[col + 1];
                        v00 += bz0; v01 += bz1; v10 += bz0; v11 += bz1;
                    }
                    if (EPI == 1) {
                        v00 = softplusf_(v00); v01 = softplusf_(v01);
                        v10 = softplusf_(v10); v11 = softplusf_(v11);
                    } else if (EPI == 2) {
                        const float* r0 = p.resid + (size_t)row * ldc + coff + col;
                        const float* r1 = p.resid + (size_t)(row + 8) * ldc + coff + col;
                        v00 += r0[0]; v01 += r0[1]; v10 += r1[0]; v11 += r1[1];
                    } else if (EPI == 3) {
                        v00 = gelu_tanh(v00); v01 = gelu_tanh(v01);
                        v10 = gelu_tanh(v10); v11 = gelu_tanh(v11);
                    }
                    if (OUTH) {
                        *(__half2*)&Ch[(size_t)row * ldc + coff + col]       = __floats2half2_rn(v00, v01);
                        *(__half2*)&Ch[(size_t)(row + 8) * ldc + coff + col] = __floats2half2_rn(v10, v11);
                    } else {
                        *(float2*)&Cf[(size_t)row * ldc + coff + col]       = make_float2(v00, v01);
                        *(float2*)&Cf[(size_t)(row + 8) * ldc + coff + col] = make_float2(v10, v11);
                    }
                }
            }
        }
    }
}

// ---------------- split-K reduce for x-proj (fp16 out only) ----------------
__global__ void reduce_xd(const float* __restrict__ part, __half* __restrict__ xd16)
{
    int gid = blockIdx.x * 256 + threadIdx.x;
    if (gid >= 2 * MT * 64) return;
    int dir = gid / (MT * 64);
    int i = gid - dir * (MT * 64);
    const float* base = part + (size_t)dir * MT * 64 + i;
    float s = 0.f;
    #pragma unroll
    for (int sp = 0; sp < NSPLIT; sp++)
        s += base[(size_t)sp * 2 * MT * 64];
    xd16[gid] = __float2half(s);
}

// ---------------- depthwise causal conv + SiLU (fp16 in/out, 2 ch/thread) ----------------
__global__ void __launch_bounds__(256) conv_kernel(
    const __half* __restrict__ xz16a, const __half* __restrict__ xz16b,
    const float* __restrict__ w0, const float* __restrict__ w1,
    const float* __restrict__ cb0, const float* __restrict__ cb1,
    __half* __restrict__ u16)
{
    const int dir = blockIdx.y;
    const __half* xz = dir ? xz16b : xz16a;
    const float* w  = dir ? w1  : w0;
    const float* cb = dir ? cb1 : cb0;

    int i = blockIdx.x * 256 + threadIdx.x;
    if (i >= MT * (DI / 2)) return;
    int cp = i % (DI / 2);
    int row = i / (DI / 2);
    int n = row % NN, b = row / NN;
    int c = cp * 2;

    float4 w0v = *(const float4*)(w + c * 4);
    float4 w1v = *(const float4*)(w + (c + 1) * 4);
    float2 cbv = *(const float2*)(cb + c);
    float a0 = cbv.x, a1 = cbv.y;
    const __half* xbase = xz + (size_t)b * NN * 2 * DI + c;

    #pragma unroll
    for (int k = 0; k < 4; k++) {
        int nn = dir ? (n + 3 - k) : (n - 3 + k);
        if (nn >= 0 && nn < NN) {
            __half2 v = *(const __half2*)(xbase + (size_t)nn * 2 * DI);
            float2 vf = __half22float2(v);
            float wk0 = (k == 0) ? w0v.x : (k == 1) ? w0v.y : (k == 2) ? w0v.z : w0v.w;
            float wk1 = (k == 0) ? w1v.x : (k == 1) ? w1v.y : (k == 2) ? w1v.z : w1v.w;
            a0 += vf.x * wk0;
            a1 += vf.y * wk1;
        }
    }
    a0 *= sigmoidf_(a0);
    a1 *= sigmoidf_(a1);
    *(__half2*)(u16 + (size_t)dir * MT * DI + (size_t)row * DI + c) = __floats2half2_rn(a0, a1);
}

// ---------------- selective scan (4 steps per iteration, PF=8, fp16 in/out) --------------
#define CPCOMMIT() asm volatile("cp.async.commit_group;\n")
#define CP8(dst, src) \
    asm volatile("cp.async.ca.shared.global [%0], [%1], 8;\n" :: "r"(dst), "l"(src))
#define PF 8
__global__ void __launch_bounds__(512, 1) scan_kernel(
    const __half* __restrict__ u16, const __half* __restrict__ dt16,
    const __half* __restrict__ xd16,
    const __half* __restrict__ xz16a, const __half* __restrict__ xz16b,
    const float* __restrict__ Al0, const float* __restrict__ Al1,
    const float* __restrict__ D0p, const float* __restrict__ D1p,
    __half* __restrict__ y16)
{
    const int dir = blockIdx.y;
    const __half* up   = u16 + (size_t)dir * MT * DI;
    const __half* dtp  = dt16 + (size_t)dir * MT * DI;
    const __half* xdp  = xd16 + (size_t)dir * MT * 64;
    const __half* xzp  = dir ? xz16b : xz16a;
    const float* Alog = dir ? Al1  : Al0;
    const float* Dp   = dir ? D1p  : D0p;
    __half* yp        = y16 + (size_t)dir * MT * DI;

    __shared__ __align__(16) __half sm[PF][224];
    const int bi = blockIdx.x >> 4;
    const int cb = (blockIdx.x & 15) << 6;
    const int tid = threadIdx.x;
    const int s = tid & 15;
    const int cl0 = tid >> 4;
    const int c0 = cb + cl0, c1 = c0 + 32;

    const float A0 = -__expf(Alog[c0 * DS + s]);
    const float A1 = -__expf(Alog[c1 * DS + s]);
    const float Dc0 = Dp[c0], Dc1 = Dp[c1];
    float h0 = 0.f, h1 = 0.f;

    auto issue = [&](int stage, int n) {
        if (tid < 56) {
            int row = bi * NN + n;
            const __half* src;
            int off;
            if (tid < 16)      { src = dtp + (size_t)row * DI + cb + tid * 4;                 off = tid * 4; }
            else if (tid < 32) { src = up  + (size_t)row * DI + cb + (tid - 16) * 4;          off = 64 + (tid - 16) * 4; }
            else if (tid < 48) { src = xzp + (size_t)row * 2 * DI + DI + cb + (tid - 32) * 4; off = 128 + (tid - 32) * 4; }
            else if (tid < 52) { src = xdp + (size_t)row * 64 + 32 + (tid - 48) * 4;          off = 192 + (tid - 48) * 4; }
            else               { src = xdp + (size_t)row * 64 + 48 + (tid - 52) * 4;          off = 208 + (tid - 52) * 4; }
            uint32_t d = (uint32_t)__cvta_generic_to_shared(&sm[stage][off]);
            CP8(d, src);
        }
    };
    #define NIDX(st) (dir ? (NN - 1 - (st)) : (st))

    issue(0, NIDX(0)); CPCOMMIT();
    issue(1, NIDX(1)); CPCOMMIT();
    issue(2, NIDX(2)); CPCOMMIT();
    issue(3, NIDX(3)); CPCOMMIT();

    for (int j = 0; j < NN; j += 4) {
        #pragma unroll
        for (int q = 0; q < 4; q++) {
            if (j + 4 + q < NN) issue((j + 4 + q) & 7, NIDX(j + 4 + q));
            CPCOMMIT();
        }
        asm volatile("cp.async.wait_group 4;\n");
        __syncthreads();

        const __half* S[4] = { sm[j & 7], sm[(j + 1) & 7], sm[(j + 2) & 7], sm[(j + 3) & 7] };

        float dt0v[4], dt1v[4], u0v[4], u1v[4], Bv[4], Cv[4];
        #pragma unroll
        for (int q = 0; q < 4; q++) {
            dt0v[q] = __half2float(S[q][cl0]);
            dt1v[q] = __half2float(S[q][32 + cl0]);
            u0v[q]  = __half2float(S[q][64 + cl0]);
            u1v[q]  = __half2float(S[q][96 + cl0]);
            Bv[q]   = __half2float(S[q][192 + s]);
            Cv[q]   = __half2float(S[q][208 + s]);
        }

        // all 8 exps are independent of the h chain -> issue first
        float e0[4], e1[4];
        #pragma unroll
        for (int q = 0; q < 4; q++) {
            e0[q] = __expf(dt0v[q] * A0);
            e1[q] = __expf(dt1v[q] * A1);
        }

        float y0[4], y1[4];
        #pragma unroll
        for (int q = 0; q < 4; q++) {
            h0 = e0[q] * h0 + dt0v[q] * Bv[q] * u0v[q];
            h1 = e1[q] * h1 + dt1v[q] * Bv[q] * u1v[q];
            y0[q] = h0 * Cv[q];
            y1[q] = h1 * Cv[q];
        }

        #pragma unroll
        for (int o = 8; o; o >>= 1) {
            #pragma unroll
            for (int q = 0; q < 4; q++) {
                y0[q] += __shfl_xor_sync(0xffffffffu, y0[q], o);
                y1[q] += __shfl_xor_sync(0xffffffffu, y1[q], o);
            }
        }
        if (s == 0) {
            #pragma unroll
            for (int q = 0; q < 4; q++) {
                int row = bi * NN + NIDX(j + q);
                float z0 = __half2float(S[q][128 + cl0]);
                float z1 = __half2float(S[q][160 + cl0]);
                yp[(size_t)row * DI + c0] = __float2half((y0[q] + u0v[q] * Dc0) * (z0 * sigmoidf_(z0)));
                yp[(size_t)row * DI + c1] = __float2half((y1[q] + u1v[q] * Dc1) * (z1 * sigmoidf_(z1)));
            }
        }
    }
    #undef NIDX
}

// ---------------- host: tensormap construction (fp16) ----------------
typedef CUresult (*PFN_encodeTiled)(
    CUtensorMap*, CUtensorMapDataType, cuuint32_t, void*,
    const cuuint64_t*, const cuuint64_t*, const cuuint32_t*, const cuuint32_t*,
    CUtensorMapInterleave, CUtensorMapSwizzle, CUtensorMapL2promotion,
    CUtensorMapFloatOOBfill);

static PFN_encodeTiled get_encoder() {
    static PFN_encodeTiled fn = nullptr;
    if (!fn) {
        void* p = nullptr;
        cudaDriverEntryPointQueryResult qr;
#if CUDART_VERSION >= 12050
        cudaGetDriverEntryPointByVersion("cuTensorMapEncodeTiled", &p, 12000,
                                         cudaEnableDefault, &qr);
#else
        cudaGetDriverEntryPoint("cuTensorMapEncodeTiled", &p, cudaEnableDefault, &qr);
#endif
        fn = (PFN_encodeTiled)p;
    }
    return fn;
}

static void enc_map16(CUtensorMap* m, const void* ptr, uint64_t d0, uint64_t d1, uint32_t b1) {
    cuuint64_t dims[2] = {d0, d1};
    cuuint64_t strides[1] = {d0 * 2};
    cuuint32_t box[2] = {64u, b1};
    cuuint32_t es[2] = {1u, 1u};
    get_encoder()(m, CU_TENSOR_MAP_DATA_TYPE_FLOAT16, 2, (void*)ptr,
                  dims, strides, box, es,
                  CU_TENSOR_MAP_INTERLEAVE_NONE, CU_TENSOR_MAP_SWIZZLE_128B,
                  CU_TENSOR_MAP_L2_PROMOTION_L2_128B, CU_TENSOR_MAP_FLOAT_OOB_FILL_NONE);
}

// ---------------- launch ----------------
extern "C" void kernel_launch(void* const* d_in, const int* in_sizes, int n_in,
                              void* d_out, int out_size) {
    const float* x  = (const float*)d_in[0];
    const float* g1 = (const float*)d_in[1];
    const float* b1 = (const float*)d_in[2];
    const float* g2 = (const float*)d_in[3];
    const float* b2 = (const float*)d_in[4];

    int base_f, base_r, base_m;
    if (in_sizes[5] == DM * 2 * DM) {        // merge_W first => dict order
        base_m = 5; base_f = 11; base_r = 20;
    } else {                                  // f_Win first => signature order
        base_f = 5; base_r = 14; base_m = 23;
    }
    const float *Win[2], *convw[2], *convb[2], *Wx[2], *Wdt[2], *bdt[2], *Alog[2], *Dp[2], *Wout[2];
    int bases[2] = {base_f, base_r};
    for (int d = 0; d < 2; d++) {
        int bs = bases[d];
        Win[d]   = (const float*)d_in[bs + 0];
        convw[d] = (const float*)d_in[bs + 1];
        convb[d] = (const float*)d_in[bs + 2];
        Wx[d]    = (const float*)d_in[bs + 3];
        Wdt[d]   = (const float*)d_in[bs + 4];
        bdt[d]   = (const float*)d_in[bs + 5];
        Alog[d]  = (const float*)d_in[bs + 6];
        Dp[d]    = (const float*)d_in[bs + 7];
        Wout[d]  = (const float*)d_in[bs + 8];
    }
    const float* merge_W = (const float*)d_in[base_m + 0];
    const float* merge_b = (const float*)d_in[base_m + 1];
    const float* ffn_W1  = (const float*)d_in[base_m + 2];
    const float* ffn_b1  = (const float*)d_in[base_m + 3];
    const float* ffn_W2  = (const float*)d_in[base_m + 4];
    const float* ffn_b2  = (const float*)d_in[base_m + 5];

    float* ws = nullptr;
    cudaGetSymbolAddress((void**)&ws, g_ws);
    __half* wh = nullptr;
    cudaGetSymbolAddress((void**)&wh, g_wsh);

    float* x1  = ws + OFF_X1;
    float* part = ws + OFF_PART;

    __half* xn16   = wh + HOFF_XN;
    __half* xz16   = wh + HOFF_XZ;
    __half* u16    = wh + HOFF_U;
    __half* dt16   = wh + HOFF_DT;
    __half* xd16   = wh + HOFF_XD;
    __half* y16    = wh + HOFF_Y;
    __half* cat16  = wh + HOFF_CAT;
    __half* xn216  = wh + HOFF_XN2;
    __half* hff16  = wh + HOFF_HFF;
    __half* Win16  = wh + HOFF_WIN;
    __half* Wx16   = wh + HOFF_WX;
    __half* Wdt16  = wh + HOFF_WDT;
    __half* Wo16   = wh + HOFF_WO;
    __half* mW16   = wh + HOFF_MW;
    __half* W116   = wh + HOFF_W1;
    __half* W216   = wh + HOFF_W2;

    cudaFuncSetAttribute((void*)mm_tma<0,128,1,3>, cudaFuncAttributeMaxDynamicSharedMemorySize, SMEM_OF(128,3));
    cudaFuncSetAttribute((void*)mm_tma<1,128,1,3>, cudaFuncAttributeMaxDynamicSharedMemorySize, SMEM_OF(128,3));
    cudaFuncSetAttribute((void*)mm_tma<3,128,1,3>, cudaFuncAttributeMaxDynamicSharedMemorySize, SMEM_OF(128,3));
    cudaFuncSetAttribute((void*)mm_tma<0,64,0,4>,  cudaFuncAttributeMaxDynamicSharedMemorySize, SMEM_OF(64,4));
    cudaFuncSetAttribute((void*)mm_tma<0,64,1,4>,  cudaFuncAttributeMaxDynamicSharedMemorySize, SMEM_OF(64,4));
    cudaFuncSetAttribute((void*)mm_tma<2,64,0,4>,  cudaFuncAttributeMaxDynamicSharedMemorySize, SMEM_OF(64,4));

    // ---- weight conversion (fp32 -> fp16) ----
    {
        CvtTab tab;
        tab.e[0]  = {Win[0],  Win16,                2 * DI, DM,   DM};
        tab.e[1]  = {Win[1],  Win16 + 2 * DI * DM,  2 * DI, DM,   DM};
        tab.e[2]  = {Wx[0],   Wx16,                 64,     DI,   DI};
        tab.e[3]  = {Wx[1],   Wx16 + 64 * DI,       64,     DI,   DI};
        tab.e[4]  = {Wdt[0],  Wdt16,                DI,     DTR,  64};
        tab.e[5]  = {Wdt[1],  Wdt16 + DI * 64,      DI,     DTR,  64};
        tab.e[6]  = {Wout[0], Wo16,                 DM,     DI,   DI};
        tab.e[7]  = {Wout[1], Wo16 + DM * DI,       DM,     DI,   DI};
        tab.e[8]  = {merge_W, mW16,                 DM,     2*DM, 2*DM};
        tab.e[9]  = {ffn_W1,  W116,                 4 * DM, DM,   DM};
        tab.e[10] = {ffn_W2,  W216,                 DM,     4*DM, 4*DM};
        cvt_kernel<<<dim3(256, 11), 256>>>(tab);
    }

    // ---- tensormaps (all fp16) ----
    CUtensorMap map_xn, map_Win0, map_Win1, map_u0, map_u1, map_Wx0, map_Wx1;
    CUtensorMap map_xd0, map_xd1, map_Wdt0, map_Wdt1, map_y0, map_y1, map_Wo0, map_Wo1;
    CUtensorMap map_cat, map_mW, map_xn2, map_W1, map_hff, map_W2;
    enc_map16(&map_xn,  xn16,             DM,     MT,   128);
    enc_map16(&map_Win0, Win16,           DM,     2*DI, 128);
    enc_map16(&map_Win1, Win16 + 2*DI*DM, DM,     2*DI, 128);
    enc_map16(&map_u0,  u16,              DI,     MT,   128);
    enc_map16(&map_u1,  u16 + MT*DI,      DI,     MT,   128);
    enc_map16(&map_Wx0, Wx16,             DI,     64,   64);
    enc_map16(&map_Wx1, Wx16 + 64*DI,     DI,     64,   64);
    enc_map16(&map_xd0, xd16,             64,     MT,   128);
    enc_map16(&map_xd1, xd16 + MT*64,     64,     MT,   128);
    enc_map16(&map_Wdt0, Wdt16,           64,     DI,   128);
    enc_map16(&map_Wdt1, Wdt16 + DI*64,   64,     DI,   128);
    enc_map16(&map_y0,  y16,              DI,     MT,   128);
    enc_map16(&map_y1,  y16 + MT*DI,      DI,     MT,   128);
    enc_map16(&map_Wo0, Wo16,             DI,     DM,   64);
    enc_map16(&map_Wo1, Wo16 + DM*DI,     DI,     DM,   64);
    enc_map16(&map_cat, cat16,            2*DM,   MT,   128);
    enc_map16(&map_mW,  mW16,             2*DM,   DM,   64);
    enc_map16(&map_xn2, xn216,            DM,     MT,   128);
    enc_map16(&map_W1,  W116,             DM,     4*DM, 128);
    enc_map16(&map_hff, hff16,            4*DM,   MT,   128);
    enc_map16(&map_W2,  W216,             4*DM,   DM,   64);

    const int MTB = MT / 128;  // 18

    ln_kernel<<<MT, 256>>>(x, g1, b1, xn16);

    // in-proj both dirs: N=2048, K=512 -> xz16
    {
        PtrSet a{nullptr, nullptr, xz16};
        PtrSet b{nullptr, nullptr, xz16 + (size_t)MT * 2 * DI};
        mm_tma<0,128,1,3><<<dim3(MTB, 16, 2), NTHREADS, SMEM_OF(128,3)>>>(
            map_xn, map_xn, map_Win0, map_Win1, a, b, 2 * DI, 0, 2 * DI, DM, 0, 0);
    }

    conv_kernel<<<dim3((MT * DI / 2 + 255) / 256, 2), 256>>>(
        xz16, xz16 + (size_t)MT * 2 * DI, convw[0], convw[1], convb[0], convb[1], u16);

    // x-proj: N=64, split-K=4 -> part fp32
    {
        PtrSet a{nullptr, nullptr, part};
        PtrSet b{nullptr, nullptr, part + (size_t)MT * 64};
        mm_tma<0,64,0,4><<<dim3(MTB, 1, 2 * NSPLIT), NTHREADS, SMEM_OF(64,4)>>>(
            map_u0, map_u1, map_Wx0, map_Wx1, a, b, 64, 0, 64, DI / NSPLIT,
            DI / NSPLIT, 2 * MT * 64);
    }
    reduce_xd<<<(2 * MT * 64 + 255) / 256, 256>>>(part, xd16);

    // dt-proj + softplus: N=1024, K=64 (padded) -> dt16
    {
        PtrSet a{bdt[0], nullptr, dt16};
        PtrSet b{bdt[1], nullptr, dt16 + (size_t)MT * DI};
        mm_tma<1,128,1,3><<<dim3(MTB, 8, 2), NTHREADS, SMEM_OF(128,3)>>>(
            map_xd0, map_xd1, map_Wdt0, map_Wdt1, a, b, DI, 0, DI, 64, 0, 0);
    }

    scan_kernel<<<dim3(BB * (DI / 64), 2), 512>>>(
        u16, dt16, xd16, xz16, xz16 + (size_t)MT * 2 * DI,
        Alog[0], Alog[1], Dp[0], Dp[1], y16);

    // out-proj both dirs -> cat16, N=512 per dir
    {
        PtrSet a{nullptr, nullptr, cat16};
        PtrSet b{nullptr, nullptr, cat16};
        mm_tma<0,64,1,4><<<dim3(MTB, 8, 2), NTHREADS, SMEM_OF(64,4)>>>(
            map_y0, map_y1, map_Wo0, map_Wo1, a, b, 2 * DM, DM, DM, DI, 0, 0);
    }

    // merge + residual -> x1 fp32
    {
        PtrSet a{merge_b, x, x1};
        mm_tma<2,64,0,4><<<dim3(MTB, 8, 1), NTHREADS, SMEM_OF(64,4)>>>(
            map_cat, map_cat, map_mW, map_mW, a, a, DM, 0, DM, 2 * DM, 0, 0);
    }

    ln_kernel<<<MT, 256>>>(x1, g2, b2, xn216);

    // ffn1 + gelu -> hff16
    {
        PtrSet a{ffn_b1, nullptr, hff16};
        mm_tma<3,128,1,3><<<dim3(MTB, 16, 1), NTHREADS, SMEM_OF(128,3)>>>(
            map_xn2, map_xn2, map_W1, map_W1, a, a, 4 * DM, 0, 4 * DM, DM, 0, 0);
    }
    // ffn2 + residual -> out fp32
    {
        PtrSet a{ffn_b2, x1, (float*)d_out};
        mm_tma<2,64,0,4><<<dim3(MTB, 8, 1), NTHREADS, SMEM_OF(64,4)>>>(
            map_hff, map_hff, map_W2, map_W2, a, a, DM, 0, DM, 4 * DM, 0, 0);
    }
}

// round 17
// speedup vs baseline: 1.0856x; 1.0125x over previous
#include <cuda_runtime.h>
#include <cuda.h>
#include <cuda_fp16.h>
#include <cstdint>

#define BB 4
#define NN 576
#define DM 512
#define DI 1024
#define DS 16
#define DTR 32
#define MT (BB*NN)   // 2304 tokens
#define NSPLIT 4

// ---------------- fp32 workspace ----------------
#define SZ_X1   (MT*DM)
#define SZ_PART (2*NSPLIT*MT*64)
#define OFF_X1   0
#define OFF_PART (OFF_X1 + SZ_X1)
#define WS_TOTAL (OFF_PART + SZ_PART)

__device__ float g_ws[WS_TOTAL];

// ---------------- fp16 workspace ----------------
#define HOFF_XN   0
#define HOFF_XZ   (HOFF_XN + MT*DM)
#define HOFF_U    (HOFF_XZ + 2*MT*2*DI)
#define HOFF_DT   (HOFF_U + 2*MT*DI)
#define HOFF_XD   (HOFF_DT + 2*MT*DI)
#define HOFF_Y    (HOFF_XD + 2*MT*64)
#define HOFF_CAT  (HOFF_Y + 2*MT*DI)
#define HOFF_XN2  (HOFF_CAT + MT*2*DM)
#define HOFF_HFF  (HOFF_XN2 + MT*DM)
#define HOFF_WIN  (HOFF_HFF + MT*4*DM)
#define HOFF_WX   (HOFF_WIN + 2*2*DI*DM)
#define HOFF_WDT  (HOFF_WX + 2*64*DI)
#define HOFF_WO   (HOFF_WDT + 2*DI*64)
#define HOFF_MW   (HOFF_WO + 2*DM*DI)
#define HOFF_W1   (HOFF_MW + DM*2*DM)
#define HOFF_W2   (HOFF_W1 + 4*DM*DM)
#define H_TOTAL   (HOFF_W2 + DM*4*DM)

__device__ __align__(1024) __half g_wsh[H_TOTAL];

// ---------------- helpers ----------------
__device__ __forceinline__ float sigmoidf_(float x) { return 1.f / (1.f + __expf(-x)); }
__device__ __forceinline__ float softplusf_(float x) {
    return fmaxf(x, 0.f) + log1pf(__expf(-fabsf(x)));
}
__device__ __forceinline__ float gelu_tanh(float x) {
    float x3 = x * x * x;
    return 0.5f * x * (1.f + tanhf(0.7978845608028654f * (x + 0.044715f * x3)));
}

// ---------------- weight conversion (fp32 -> fp16, optional K padding) ----------------
struct Cvt { const float* s; __half* d; int rows; int sk; int dk; };
struct CvtTab { Cvt e[11]; };

__global__ void cvt_kernel(CvtTab tab) {
    Cvt c = tab.e[blockIdx.y];
    int total = c.rows * c.dk;
    for (int idx = blockIdx.x * 256 + threadIdx.x; idx < total; idx += gridDim.x * 256) {
        int row = idx / c.dk, col = idx - row * c.dk;
        float v = (col < c.sk) ? c.s[(size_t)row * c.sk + col] : 0.f;
        c.d[idx] = __float2half(v);
    }
}

// ---------------- LayerNorm (fp16 out) ----------------
__global__ void ln_kernel(const float* __restrict__ x, const float* __restrict__ g,
                          const float* __restrict__ b, __half* __restrict__ out) {
    int row = blockIdx.x;
    int t = threadIdx.x;              // 256 threads
    const float* xr = x + row * DM;
    float v0 = xr[t], v1 = xr[t + 256];
    float s = v0 + v1, q = v0 * v0 + v1 * v1;
    #pragma unroll
    for (int o = 16; o; o >>= 1) {
        s += __shfl_xor_sync(0xffffffffu, s, o);
        q += __shfl_xor_sync(0xffffffffu, q, o);
    }
    __shared__ float ss[8], qq[8];
    int w = t >> 5;
    if ((t & 31) == 0) { ss[w] = s; qq[w] = q; }
    __syncthreads();
    s = 0.f; q = 0.f;
    #pragma unroll
    for (int i = 0; i < 8; i++) { s += ss[i]; q += qq[i]; }
    float mean = s * (1.f / DM);
    float var = q * (1.f / DM) - mean * mean;
    float inv = rsqrtf(var + 1e-5f);
    out[row * DM + t]       = __float2half((v0 - mean) * inv * g[t] + b[t]);
    out[row * DM + t + 256] = __float2half((v1 - mean) * inv * g[t + 256] + b[t + 256]);
}

// ---------------- mbarrier / TMA primitives ----------------
#define MBINIT(addr, cnt) \
    asm volatile("mbarrier.init.shared.b64 [%0], %1;" :: "r"(addr), "r"(cnt) : "memory")
#define MBEXPECT(addr, bytes) \
    asm volatile("mbarrier.arrive.expect_tx.shared.b64 _, [%0], %1;" :: "r"(addr), "r"(bytes) : "memory")
#define MBARRIVE(addr) \
    asm volatile("mbarrier.arrive.shared.b64 _, [%0];" :: "r"(addr) : "memory")

__device__ __forceinline__ void mbar_wait(uint32_t addr, uint32_t phase) {
    asm volatile(
        "{\n\t.reg .pred p;\n\t"
        "LW%=:\n\t"
        "mbarrier.try_wait.parity.shared.b64 p, [%0], %1;\n\t"
        "@!p bra LW%=;\n\t}"
        :: "r"(addr), "r"(phase) : "memory");
}

__device__ __forceinline__ void tma2d(uint32_t dst, const CUtensorMap* m, int cx, int cy, uint32_t bar) {
    asm volatile(
        "cp.async.bulk.tensor.2d.shared::cta.global.tile.mbarrier::complete_tx::bytes "
        "[%0], [%1, {%2, %3}], [%4];"
        :: "r"(dst), "l"(m), "r"(cx), "r"(cy), "r"(bar) : "memory");
}

// ---------------- fp16 tensor-core GEMM (TMA + producer warp, 128xNTILE tile) ------------
// EPI: 0 none, 1 bias+softplus, 2 bias+residual, 3 bias+gelu ; OUTH: fp16 output
struct PtrSet {
    const float* bias;
    const float* resid;
    void* C;
};

__device__ __forceinline__ void mma16(float (&d)[4], const uint32_t (&a)[4], const uint32_t (&b)[2]) {
    asm volatile(
        "mma.sync.aligned.m16n8k16.row.col.f32.f16.f16.f32 "
        "{%0,%1,%2,%3}, {%4,%5,%6,%7}, {%8,%9}, {%0,%1,%2,%3};\n"
        : "+f"(d[0]), "+f"(d[1]), "+f"(d[2]), "+f"(d[3])
        : "r"(a[0]), "r"(a[1]), "r"(a[2]), "r"(a[3]),
          "r"(b[0]), "r"(b[1]));
}

__device__ __forceinline__ void ldsm4(uint32_t (&r)[4], uint32_t addr) {
    asm volatile("ldmatrix.sync.aligned.m8n8.x4.shared.b16 {%0,%1,%2,%3}, [%4];\n"
                 : "=r"(r[0]), "=r"(r[1]), "=r"(r[2]), "=r"(r[3]) : "r"(addr));
}

#define SLAB_A 16384u               // 128 rows x 128B (64 fp16/row)
#define NTHREADS 288                // 8 compute warps + 1 producer warp
#define SMEM_OF(NTILE, STGN) ((unsigned)(STGN) * (SLAB_A + (unsigned)(NTILE) * 128u) + 1024)

template <int EPI, int NTILE, int OUTH, int STGN>
__global__ void __launch_bounds__(NTHREADS, 2) mm_tma(
    const __grid_constant__ CUtensorMap mA0, const __grid_constant__ CUtensorMap mA1,
    const __grid_constant__ CUtensorMap mW0, const __grid_constant__ CUtensorMap mW1,
    PtrSet p0, PtrSet p1, int ldc, int coffStep, int N, int Ksplit,
    int kbaseStep, int csplitStep)
{
    extern __shared__ float dynsm[];
    __shared__ __align__(8) uint64_t mb[2 * STGN];

    constexpr uint32_t SLAB_B = (uint32_t)NTILE * 128u;
    constexpr uint32_t SST = SLAB_A + SLAB_B;
    constexpr int WN = NTILE / 2;
    constexpr int NTL = NTILE / 16;
    constexpr int NPQ = NTILE / 32;

    const int dir = blockIdx.z & 1;
    const int split = blockIdx.z >> 1;
    const CUtensorMap* tA = dir ? &mA1 : &mA0;
    const CUtensorMap* tW = dir ? &mW1 : &mW0;
    const PtrSet p = dir ? p1 : p0;
    const int coff = dir * coffStep;
    const int kbase = split * kbaseStep;

    const int tid = threadIdx.x;
    const int lane = tid & 31;
    const int wid = tid >> 5;
    const int wr = wid & 3;
    const int wc = (wid >> 2) & 1;
    const int g = lane >> 2;
    const int t = lane & 3;

    const int m0 = blockIdx.x * 128;
    const int n0 = blockIdx.y * NTILE;

    uint32_t raw = (uint32_t)__cvta_generic_to_shared(dynsm);
    const uint32_t sbase = (raw + 1023u) & ~1023u;
    const uint32_t mbb = (uint32_t)__cvta_generic_to_shared(&mb[0]);

    const int nc = Ksplit >> 6;

    if (tid == 0) {
        #pragma unroll
        for (int s = 0; s < STGN; s++) {
            MBINIT(mbb + s * 8, 1);
            MBINIT(mbb + (STGN + s) * 8, 8);
        }
    }
    __syncthreads();

    if (wid == 8) {
        if (lane == 0) {
            for (int c = 0; c < nc; c++) {
                int s = c % STGN;
                uint32_t ph = 1u ^ (uint32_t)((c / STGN) & 1);
                mbar_wait(mbb + (STGN + s) * 8, ph);
                MBEXPECT(mbb + s * 8, SST);
                tma2d(sbase + s * SST,          tA, kbase + c * 64, m0, mbb + s * 8);
                tma2d(sbase + s * SST + SLAB_A, tW, kbase + c * 64, n0, mbb + s * 8);
            }
        }
    } else {
        const uint32_t asw = (uint32_t)((lane & 7) << 4);
        const uint32_t awb = (uint32_t)(wr * 4096 + (lane & 15) * 128);
        const uint32_t ua  = (uint32_t)(lane >> 4);
        const uint32_t bwb = (uint32_t)((wc * WN + (lane & 7) + ((lane >> 4) << 3)) * 128);
        const uint32_t ub  = (uint32_t)((lane >> 3) & 1);

        float d[2][NTL][4];
        #pragma unroll
        for (int i = 0; i < 2; i++)
            #pragma unroll
            for (int j = 0; j < NTL; j++)
                #pragma unroll
                for (int r = 0; r < 4; r++) d[i][j][r] = 0.f;

        for (int c = 0; c < nc; c++) {
            int s = c % STGN;
            mbar_wait(mbb + s * 8, (uint32_t)((c / STGN) & 1));
            const uint32_t sa = sbase + s * SST;
            const uint32_t sbB = sa + SLAB_A;
            #pragma unroll
            for (int kk = 0; kk < 4; kk++) {
                uint32_t a[2][4];
                uint32_t b[NTL][2];
                uint32_t aoff = (((ua + kk * 2) << 4) ^ asw);
                #pragma unroll
                for (int mt = 0; mt < 2; mt++)
                    ldsm4(a[mt], sa + awb + mt * 2048 + aoff);
                uint32_t boff = (((ub + kk * 2) << 4) ^ asw);
                #pragma unroll
                for (int np = 0; np < NPQ; np++) {
                    uint32_t r[4];
                    ldsm4(r, sbB + bwb + np * 2048 + boff);
                    b[2 * np][0] = r[0]; b[2 * np][1] = r[1];
                    b[2 * np + 1][0] = r[2]; b[2 * np + 1][1] = r[3];
                }
                if (kk == 3 && lane == 0) MBARRIVE(mbb + (STGN + s) * 8);
                #pragma unroll
                for (int mt = 0; mt < 2; mt++)
                    #pragma unroll
                    for (int nt = 0; nt < NTL; nt++)
                        mma16(d[mt][nt], a[mt], b[nt]);
            }
        }

        // -------- epilogue --------
        float* Cf = (float*)p.C + (size_t)split * csplitStep;
        __half* Ch = (__half*)p.C;
        #pragma unroll
        for (int mt = 0; mt < 2; mt++) {
            const int row = m0 + wr * 32 + mt * 16 + g;
            #pragma unroll
            for (int nt = 0; nt < NTL; nt++) {
                const int col = n0 + wc * WN + nt * 8 + 2 * t;
                if (col < N) {
                    float v00 = d[mt][nt][0], v01 = d[mt][nt][1];
                    float v10 = d[mt][nt][2], v11 = d[mt][nt][3];
                    if (EPI != 0) {
                        float bz0 = p.bias[col], bz1 = p.bias[col + 1];
                        v00 += bz0; v01 += bz1; v10 += bz0; v11 += bz1;
                    }
                    if (EPI == 1) {
                        v00 = softplusf_(v00); v01 = softplusf_(v01);
                        v10 = softplusf_(v10); v11 = softplusf_(v11);
                    } else if (EPI == 2) {
                        const float* r0 = p.resid + (size_t)row * ldc + coff + col;
                        const float* r1 = p.resid + (size_t)(row + 8) * ldc + coff + col;
                        v00 += r0[0]; v01 += r0[1]; v10 += r1[0]; v11 += r1[1];
                    } else if (EPI == 3) {
                        v00 = gelu_tanh(v00); v01 = gelu_tanh(v01);
                        v10 = gelu_tanh(v10); v11 = gelu_tanh(v11);
                    }
                    if (OUTH) {
                        *(__half2*)&Ch[(size_t)row * ldc + coff + col]       = __floats2half2_rn(v00, v01);
                        *(__half2*)&Ch[(size_t)(row + 8) * ldc + coff + col] = __floats2half2_rn(v10, v11);
                    } else {
                        *(float2*)&Cf[(size_t)row * ldc + coff + col]       = make_float2(v00, v01);
                        *(float2*)&Cf[(size_t)(row + 8) * ldc + coff + col] = make_float2(v10, v11);
                    }
                }
            }
        }
    }
}

// ---------------- split-K reduce for x-proj (fp16 out only) ----------------
__global__ void reduce_xd(const float* __restrict__ part, __half* __restrict__ xd16)
{
    int gid = blockIdx.x * 256 + threadIdx.x;
    if (gid >= 2 * MT * 64) return;
    int dir = gid / (MT * 64);
    int i = gid - dir * (MT * 64);
    const float* base = part + (size_t)dir * MT * 64 + i;
    float s = 0.f;
    #pragma unroll
    for (int sp = 0; sp < NSPLIT; sp++)
        s += base[(size_t)sp * 2 * MT * 64];
    xd16[gid] = __float2half(s);
}

// ---------------- depthwise causal conv + SiLU (fp16, 2 ch x 4 tokens / thread) ----------
__global__ void __launch_bounds__(256) conv_kernel(
    const __half* __restrict__ xz16a, const __half* __restrict__ xz16b,
    const float* __restrict__ w0, const float* __restrict__ w1,
    const float* __restrict__ cb0, const float* __restrict__ cb1,
    __half* __restrict__ u16)
{
    const int dir = blockIdx.y;
    const __half* xz = dir ? xz16b : xz16a;
    const float* w  = dir ? w1  : w0;
    const float* cb = dir ? cb1 : cb0;

    int i = blockIdx.x * 256 + threadIdx.x;   // over (MT/4) * (DI/2)
    if (i >= (MT / 4) * (DI / 2)) return;
    int cp = i % (DI / 2);
    int rq = i / (DI / 2);
    int nq = rq % (NN / 4);
    int b  = rq / (NN / 4);
    int n0 = nq * 4;
    int c = cp * 2;

    float4 w0v = *(const float4*)(w + c * 4);
    float4 w1v = *(const float4*)(w + (c + 1) * 4);
    float wk0[4] = {w0v.x, w0v.y, w0v.z, w0v.w};
    float wk1[4] = {w1v.x, w1v.y, w1v.z, w1v.w};
    float2 cbv = *(const float2*)(cb + c);
    const __half* xbase = xz + (size_t)b * NN * 2 * DI + c;

    // 7 taps cover 4 outputs: dir0 needs n0-3..n0+3, dir1 needs n0..n0+6
    float2 xv[7];
    #pragma unroll
    for (int k = 0; k < 7; k++) {
        int nn = dir ? (n0 + k) : (n0 - 3 + k);
        if (nn >= 0 && nn < NN)
            xv[k] = __half22float2(*(const __half2*)(xbase + (size_t)nn * 2 * DI));
        else
            xv[k] = make_float2(0.f, 0.f);
    }

    __half2* ubase = (__half2*)(u16 + (size_t)dir * MT * DI
                                + (size_t)(b * NN + n0) * DI + c);
    #pragma unroll
    for (int q = 0; q < 4; q++) {
        float a0 = cbv.x, a1 = cbv.y;
        #pragma unroll
        for (int k = 0; k < 4; k++) {
            // dir0: out[n0+q] = sum_k w[k] * x[n0+q-3+k]  -> xv[q+k]
            // dir1: out[n0+q] = sum_k w[k] * x[n0+q+3-k]  -> xv[q+3-k]
            float2 v = dir ? xv[q + 3 - k] : xv[q + k];
            a0 += v.x * wk0[k];
            a1 += v.y * wk1[k];
        }
        a0 *= sigmoidf_(a0);
        a1 *= sigmoidf_(a1);
        ubase[(size_t)q * (DI / 2)] = __floats2half2_rn(a0, a1);
    }
}

// ---------------- selective scan (4 steps per iteration, PF=8, fp16 in/out) --------------
#define CPCOMMIT() asm volatile("cp.async.commit_group;\n")
#define CP8(dst, src) \
    asm volatile("cp.async.ca.shared.global [%0], [%1], 8;\n" :: "r"(dst), "l"(src))
#define PF 8
__global__ void __launch_bounds__(512, 1) scan_kernel(
    const __half* __restrict__ u16, const __half* __restrict__ dt16,
    const __half* __restrict__ xd16,
    const __half* __restrict__ xz16a, const __half* __restrict__ xz16b,
    const float* __restrict__ Al0, const float* __restrict__ Al1,
    const float* __restrict__ D0p, const float* __restrict__ D1p,
    __half* __restrict__ y16)
{
    const int dir = blockIdx.y;
    const __half* up   = u16 + (size_t)dir * MT * DI;
    const __half* dtp  = dt16 + (size_t)dir * MT * DI;
    const __half* xdp  = xd16 + (size_t)dir * MT * 64;
    const __half* xzp  = dir ? xz16b : xz16a;
    const float* Alog = dir ? Al1  : Al0;
    const float* Dp   = dir ? D1p  : D0p;
    __half* yp        = y16 + (size_t)dir * MT * DI;

    __shared__ __align__(16) __half sm[PF][224];
    const int bi = blockIdx.x >> 4;
    const int cb = (blockIdx.x & 15) << 6;
    const int tid = threadIdx.x;
    const int s = tid & 15;
    const int cl0 = tid >> 4;
    const int c0 = cb + cl0, c1 = c0 + 32;

    const float A0 = -__expf(Alog[c0 * DS + s]);
    const float A1 = -__expf(Alog[c1 * DS + s]);
    const float Dc0 = Dp[c0], Dc1 = Dp[c1];
    float h0 = 0.f, h1 = 0.f;

    auto issue = [&](int stage, int n) {
        if (tid < 56) {
            int row = bi * NN + n;
            const __half* src;
            int off;
            if (tid < 16)      { src = dtp + (size_t)row * DI + cb + tid * 4;                 off = tid * 4; }
            else if (tid < 32) { src = up  + (size_t)row * DI + cb + (tid - 16) * 4;          off = 64 + (tid - 16) * 4; }
            else if (tid < 48) { src = xzp + (size_t)row * 2 * DI + DI + cb + (tid - 32) * 4; off = 128 + (tid - 32) * 4; }
            else if (tid < 52) { src = xdp + (size_t)row * 64 + 32 + (tid - 48) * 4;          off = 192 + (tid - 48) * 4; }
            else               { src = xdp + (size_t)row * 64 + 48 + (tid - 52) * 4;          off = 208 + (tid - 52) * 4; }
            uint32_t d = (uint32_t)__cvta_generic_to_shared(&sm[stage][off]);
            CP8(d, src);
        }
    };
    #define NIDX(st) (dir ? (NN - 1 - (st)) : (st))

    issue(0, NIDX(0)); CPCOMMIT();
    issue(1, NIDX(1)); CPCOMMIT();
    issue(2, NIDX(2)); CPCOMMIT();
    issue(3, NIDX(3)); CPCOMMIT();

    for (int j = 0; j < NN; j += 4) {
        #pragma unroll
        for (int q = 0; q < 4; q++) {
            if (j + 4 + q < NN) issue((j + 4 + q) & 7, NIDX(j + 4 + q));
            CPCOMMIT();
        }
        asm volatile("cp.async.wait_group 4;\n");
        __syncthreads();

        const __half* S[4] = { sm[j & 7], sm[(j + 1) & 7], sm[(j + 2) & 7], sm[(j + 3) & 7] };

        float dt0v[4], dt1v[4], u0v[4], u1v[4], Bv[4], Cv[4];
        #pragma unroll
        for (int q = 0; q < 4; q++) {
            dt0v[q] = __half2float(S[q][cl0]);
            dt1v[q] = __half2float(S[q][32 + cl0]);
            u0v[q]  = __half2float(S[q][64 + cl0]);
            u1v[q]  = __half2float(S[q][96 + cl0]);
            Bv[q]   = __half2float(S[q][192 + s]);
            Cv[q]   = __half2float(S[q][208 + s]);
        }

        float e0[4], e1[4];
        #pragma unroll
        for (int q = 0; q < 4; q++) {
            e0[q] = __expf(dt0v[q] * A0);
            e1[q] = __expf(dt1v[q] * A1);
        }

        float y0[4], y1[4];
        #pragma unroll
        for (int q = 0; q < 4; q++) {
            h0 = e0[q] * h0 + dt0v[q] * Bv[q] * u0v[q];
            h1 = e1[q] * h1 + dt1v[q] * Bv[q] * u1v[q];
            y0[q] = h0 * Cv[q];
            y1[q] = h1 * Cv[q];
        }

        #pragma unroll
        for (int o = 8; o; o >>= 1) {
            #pragma unroll
            for (int q = 0; q < 4; q++) {
                y0[q] += __shfl_xor_sync(0xffffffffu, y0[q], o);
                y1[q] += __shfl_xor_sync(0xffffffffu, y1[q], o);
            }
        }
        if (s == 0) {
            #pragma unroll
            for (int q = 0; q < 4; q++) {
                int row = bi * NN + NIDX(j + q);
                float z0 = __half2float(S[q][128 + cl0]);
                float z1 = __half2float(S[q][160 + cl0]);
                yp[(size_t)row * DI + c0] = __float2half((y0[q] + u0v[q] * Dc0) * (z0 * sigmoidf_(z0)));
                yp[(size_t)row * DI + c1] = __float2half((y1[q] + u1v[q] * Dc1) * (z1 * sigmoidf_(z1)));
            }
        }
    }
    #undef NIDX
}

// ---------------- host: tensormap construction (fp16) ----------------
typedef CUresult (*PFN_encodeTiled)(
    CUtensorMap*, CUtensorMapDataType, cuuint32_t, void*,
    const cuuint64_t*, const cuuint64_t*, const cuuint32_t*, const cuuint32_t*,
    CUtensorMapInterleave, CUtensorMapSwizzle, CUtensorMapL2promotion,
    CUtensorMapFloatOOBfill);

static PFN_encodeTiled get_encoder() {
    static PFN_encodeTiled fn = nullptr;
    if (!fn) {
        void* p = nullptr;
        cudaDriverEntryPointQueryResult qr;
#if CUDART_VERSION >= 12050
        cudaGetDriverEntryPointByVersion("cuTensorMapEncodeTiled", &p, 12000,
                                         cudaEnableDefault, &qr);
#else
        cudaGetDriverEntryPoint("cuTensorMapEncodeTiled", &p, cudaEnableDefault, &qr);
#endif
        fn = (PFN_encodeTiled)p;
    }
    return fn;
}

static void enc_map16(CUtensorMap* m, const void* ptr, uint64_t d0, uint64_t d1, uint32_t b1) {
    cuuint64_t dims[2] = {d0, d1};
    cuuint64_t strides[1] = {d0 * 2};
    cuuint32_t box[2] = {64u, b1};
    cuuint32_t es[2] = {1u, 1u};
    get_encoder()(m, CU_TENSOR_MAP_DATA_TYPE_FLOAT16, 2, (void*)ptr,
                  dims, strides, box, es,
                  CU_TENSOR_MAP_INTERLEAVE_NONE, CU_TENSOR_MAP_SWIZZLE_128B,
                  CU_TENSOR_MAP_L2_PROMOTION_L2_128B, CU_TENSOR_MAP_FLOAT_OOB_FILL_NONE);
}

// ---------------- launch ----------------
extern "C" void kernel_launch(void* const* d_in, const int* in_sizes, int n_in,
                              void* d_out, int out_size) {
    const float* x  = (const float*)d_in[0];
    const float* g1 = (const float*)d_in[1];
    const float* b1 = (const float*)d_in[2];
    const float* g2 = (const float*)d_in[3];
    const float* b2 = (const float*)d_in[4];

    int base_f, base_r, base_m;
    if (in_sizes[5] == DM * 2 * DM) {        // merge_W first => dict order
        base_m = 5; base_f = 11; base_r = 20;
    } else {                                  // f_Win first => signature order
        base_f = 5; base_r = 14; base_m = 23;
    }
    const float *Win[2], *convw[2], *convb[2], *Wx[2], *Wdt[2], *bdt[2], *Alog[2], *Dp[2], *Wout[2];
    int bases[2] = {base_f, base_r};
    for (int d = 0; d < 2; d++) {
        int bs = bases[d];
        Win[d]   = (const float*)d_in[bs + 0];
        convw[d] = (const float*)d_in[bs + 1];
        convb[d] = (const float*)d_in[bs + 2];
        Wx[d]    = (const float*)d_in[bs + 3];
        Wdt[d]   = (const float*)d_in[bs + 4];
        bdt[d]   = (const float*)d_in[bs + 5];
        Alog[d]  = (const float*)d_in[bs + 6];
        Dp[d]    = (const float*)d_in[bs + 7];
        Wout[d]  = (const float*)d_in[bs + 8];
    }
    const float* merge_W = (const float*)d_in[base_m + 0];
    const float* merge_b = (const float*)d_in[base_m + 1];
    const float* ffn_W1  = (const float*)d_in[base_m + 2];
    const float* ffn_b1  = (const float*)d_in[base_m + 3];
    const float* ffn_W2  = (const float*)d_in[base_m + 4];
    const float* ffn_b2  = (const float*)d_in[base_m + 5];

    float* ws = nullptr;
    cudaGetSymbolAddress((void**)&ws, g_ws);
    __half* wh = nullptr;
    cudaGetSymbolAddress((void**)&wh, g_wsh);

    float* x1  = ws + OFF_X1;
    float* part = ws + OFF_PART;

    __half* xn16   = wh + HOFF_XN;
    __half* xz16   = wh + HOFF_XZ;
    __half* u16    = wh + HOFF_U;
    __half* dt16   = wh + HOFF_DT;
    __half* xd16   = wh + HOFF_XD;
    __half* y16    = wh + HOFF_Y;
    __half* cat16  = wh + HOFF_CAT;
    __half* xn216  = wh + HOFF_XN2;
    __half* hff16  = wh + HOFF_HFF;
    __half* Win16  = wh + HOFF_WIN;
    __half* Wx16   = wh + HOFF_WX;
    __half* Wdt16  = wh + HOFF_WDT;
    __half* Wo16   = wh + HOFF_WO;
    __half* mW16   = wh + HOFF_MW;
    __half* W116   = wh + HOFF_W1;
    __half* W216   = wh + HOFF_W2;

    cudaFuncSetAttribute((void*)mm_tma<0,128,1,3>, cudaFuncAttributeMaxDynamicSharedMemorySize, SMEM_OF(128,3));
    cudaFuncSetAttribute((void*)mm_tma<1,128,1,3>, cudaFuncAttributeMaxDynamicSharedMemorySize, SMEM_OF(128,3));
    cudaFuncSetAttribute((void*)mm_tma<3,128,1,3>, cudaFuncAttributeMaxDynamicSharedMemorySize, SMEM_OF(128,3));
    cudaFuncSetAttribute((void*)mm_tma<0,64,0,4>,  cudaFuncAttributeMaxDynamicSharedMemorySize, SMEM_OF(64,4));
    cudaFuncSetAttribute((void*)mm_tma<0,64,1,4>,  cudaFuncAttributeMaxDynamicSharedMemorySize, SMEM_OF(64,4));
    cudaFuncSetAttribute((void*)mm_tma<2,64,0,4>,  cudaFuncAttributeMaxDynamicSharedMemorySize, SMEM_OF(64,4));

    // ---- weight conversion (fp32 -> fp16) ----
    {
        CvtTab tab;
        tab.e[0]  = {Win[0],  Win16,                2 * DI, DM,   DM};
        tab.e[1]  = {Win[1],  Win16 + 2 * DI * DM,  2 * DI, DM,   DM};
        tab.e[2]  = {Wx[0],   Wx16,                 64,     DI,   DI};
        tab.e[3]  = {Wx[1],   Wx16 + 64 * DI,       64,     DI,   DI};
        tab.e[4]  = {Wdt[0],  Wdt16,                DI,     DTR,  64};
        tab.e[5]  = {Wdt[1],  Wdt16 + DI * 64,      DI,     DTR,  64};
        tab.e[6]  = {Wout[0], Wo16,                 DM,     DI,   DI};
        tab.e[7]  = {Wout[1], Wo16 + DM * DI,       DM,     DI,   DI};
        tab.e[8]  = {merge_W, mW16,                 DM,     2*DM, 2*DM};
        tab.e[9]  = {ffn_W1,  W116,                 4 * DM, DM,   DM};
        tab.e[10] = {ffn_W2,  W216,                 DM,     4*DM, 4*DM};
        cvt_kernel<<<dim3(256, 11), 256>>>(tab);
    }

    // ---- tensormaps (all fp16) ----
    CUtensorMap map_xn, map_Win0, map_Win1, map_u0, map_u1, map_Wx0, map_Wx1;
    CUtensorMap map_xd0, map_xd1, map_Wdt0, map_Wdt1, map_y0, map_y1, map_Wo0, map_Wo1;
    CUtensorMap map_cat, map_mW, map_xn2, map_W1, map_hff, map_W2;
    enc_map16(&map_xn,  xn16,             DM,     MT,   128);
    enc_map16(&map_Win0, Win16,           DM,     2*DI, 128);
    enc_map16(&map_Win1, Win16 + 2*DI*DM, DM,     2*DI, 128);
    enc_map16(&map_u0,  u16,              DI,     MT,   128);
    enc_map16(&map_u1,  u16 + MT*DI,      DI,     MT,   128);
    enc_map16(&map_Wx0, Wx16,             DI,     64,   64);
    enc_map16(&map_Wx1, Wx16 + 64*DI,     DI,     64,   64);
    enc_map16(&map_xd0, xd16,             64,     MT,   128);
    enc_map16(&map_xd1, xd16 + MT*64,     64,     MT,   128);
    enc_map16(&map_Wdt0, Wdt16,           64,     DI,   128);
    enc_map16(&map_Wdt1, Wdt16 + DI*64,   64,     DI,   128);
    enc_map16(&map_y0,  y16,              DI,     MT,   128);
    enc_map16(&map_y1,  y16 + MT*DI,      DI,     MT,   128);
    enc_map16(&map_Wo0, Wo16,             DI,     DM,   64);
    enc_map16(&map_Wo1, Wo16 + DM*DI,     DI,     DM,   64);
    enc_map16(&map_cat, cat16,            2*DM,   MT,   128);
    enc_map16(&map_mW,  mW16,             2*DM,   DM,   64);
    enc_map16(&map_xn2, xn216,            DM,     MT,   128);
    enc_map16(&map_W1,  W116,             DM,     4*DM, 128);
    enc_map16(&map_hff, hff16,            4*DM,   MT,   128);
    enc_map16(&map_W2,  W216,             4*DM,   DM,   64);

    const int MTB = MT / 128;  // 18

    ln_kernel<<<MT, 256>>>(x, g1, b1, xn16);

    // in-proj both dirs: N=2048, K=512 -> xz16
    {
        PtrSet a{nullptr, nullptr, xz16};
        PtrSet b{nullptr, nullptr, xz16 + (size_t)MT * 2 * DI};
        mm_tma<0,128,1,3><<<dim3(MTB, 16, 2), NTHREADS, SMEM_OF(128,3)>>>(
            map_xn, map_xn, map_Win0, map_Win1, a, b, 2 * DI, 0, 2 * DI, DM, 0, 0);
    }

    conv_kernel<<<dim3(((MT / 4) * (DI / 2) + 255) / 256, 2), 256>>>(
        xz16, xz16 + (size_t)MT * 2 * DI, convw[0], convw[1], convb[0], convb[1], u16);

    // x-proj: N=64, split-K=4 -> part fp32
    {
        PtrSet a{nullptr, nullptr, part};
        PtrSet b{nullptr, nullptr, part + (size_t)MT * 64};
        mm_tma<0,64,0,4><<<dim3(MTB, 1, 2 * NSPLIT), NTHREADS, SMEM_OF(64,4)>>>(
            map_u0, map_u1, map_Wx0, map_Wx1, a, b, 64, 0, 64, DI / NSPLIT,
            DI / NSPLIT, 2 * MT * 64);
    }
    reduce_xd<<<(2 * MT * 64 + 255) / 256, 256>>>(part, xd16);

    // dt-proj + softplus: N=1024, K=64 (padded) -> dt16
    {
        PtrSet a{bdt[0], nullptr, dt16};
        PtrSet b{bdt[1], nullptr, dt16 + (size_t)MT * DI};
        mm_tma<1,128,1,3><<<dim3(MTB, 8, 2), NTHREADS, SMEM_OF(128,3)>>>(
            map_xd0, map_xd1, map_Wdt0, map_Wdt1, a, b, DI, 0, DI, 64, 0, 0);
    }

    scan_kernel<<<dim3(BB * (DI / 64), 2), 512>>>(
        u16, dt16, xd16, xz16, xz16 + (size_t)MT * 2 * DI,
        Alog[0], Alog[1], Dp[0], Dp[1], y16);

    // out-proj both dirs -> cat16, N=512 per dir
    {
        PtrSet a{nullptr, nullptr, cat16};
        PtrSet b{nullptr, nullptr, cat16};
        mm_tma<0,64,1,4><<<dim3(MTB, 8, 2), NTHREADS, SMEM_OF(64,4)>>>(
            map_y0, map_y1, map_Wo0, map_Wo1, a, b, 2 * DM, DM, DM, DI, 0, 0);
    }

    // merge + residual -> x1 fp32
    {
        PtrSet a{merge_b, x, x1};
        mm_tma<2,64,0,4><<<dim3(MTB, 8, 1), NTHREADS, SMEM_OF(64,4)>>>(
            map_cat, map_cat, map_mW, map_mW, a, a, DM, 0, DM, 2 * DM, 0, 0);
    }

    ln_kernel<<<MT, 256>>>(x1, g2, b2, xn216);

    // ffn1 + gelu -> hff16
    {
        PtrSet a{ffn_b1, nullptr, hff16};
        mm_tma<3,128,1,3><<<dim3(MTB, 16, 1), NTHREADS, SMEM_OF(128,3)>>>(
            map_xn2, map_xn2, map_W1, map_W1, a, a, 4 * DM, 0, 4 * DM, DM, 0, 0);
    }
    // ffn2 + residual -> out fp32
    {
        PtrSet a{ffn_b2, x1, (float*)d_out};
        mm_tma<2,64,0,4><<<dim3(MTB, 8, 1), NTHREADS, SMEM_OF(64,4)>>>(
            map_hff, map_hff, map_W2, map_W2, a, a, DM, 0, DM, 4 * DM, 0, 0);
    }
}